// round 3
// baseline (speedup 1.0000x reference)
#include <cuda_runtime.h>
#include <vector>
#include <cmath>

#define HID 256
#define OLEN 192
#define NMODE 32
#define TSUM 1344
#define NCOL 12288   // 192*32*2

// ---------------- host constant tables ----------------
static float h_H[TSUM * HID];
static float h_em[3 * OLEN * HID];
static float h_tw[TSUM * 2];
static float h_al[3 * NMODE * 2];

struct HostInit {
  HostInit() {
    const double PI2 = 6.283185307179586476925286766559;
    for (int si = 0; si < 3; si++) {
      int sc = 1 << si;
      int T = OLEN * sc;
      int uoff = (si == 0) ? 0 : (si == 1) ? 192 : 576;
      double dt = 1.0 / (double)T;
      // bilinear-discretized HiPPO-LegT via augmented solve
      std::vector<double> M((size_t)HID * HID), R((size_t)HID * (HID + 1)), X((size_t)HID * (HID + 1));
      for (int r = 0; r < HID; r++) {
        for (int c = 0; c < HID; c++) {
          double a = (r < c) ? -1.0 : (((r - c) & 1) ? 1.0 : -1.0);
          a *= (2.0 * r + 1.0);
          M[(size_t)r * HID + c] = (r == c ? 1.0 : 0.0) - 0.5 * dt * a;
          R[(size_t)r * (HID + 1) + c] = (r == c ? 1.0 : 0.0) + 0.5 * dt * a;
        }
        R[(size_t)r * (HID + 1) + HID] = ((r & 1) ? -1.0 : 1.0) * (2.0 * r + 1.0) * dt;
      }
      for (int col = 0; col < HID; col++) {
        int piv = col; double mx = fabs(M[(size_t)col * HID + col]);
        for (int r = col + 1; r < HID; r++) { double v = fabs(M[(size_t)r * HID + col]); if (v > mx) { mx = v; piv = r; } }
        if (piv != col) {
          for (int c = col; c < HID; c++) { double t = M[(size_t)col*HID+c]; M[(size_t)col*HID+c] = M[(size_t)piv*HID+c]; M[(size_t)piv*HID+c] = t; }
          for (int c = 0; c <= HID; c++) { double t = R[(size_t)col*(HID+1)+c]; R[(size_t)col*(HID+1)+c] = R[(size_t)piv*(HID+1)+c]; R[(size_t)piv*(HID+1)+c] = t; }
        }
        double d = M[(size_t)col * HID + col];
        for (int r = col + 1; r < HID; r++) {
          double f = M[(size_t)r * HID + col] / d;
          if (f != 0.0) {
            for (int c = col; c < HID; c++) M[(size_t)r*HID+c] -= f * M[(size_t)col*HID+c];
            for (int c = 0; c <= HID; c++) R[(size_t)r*(HID+1)+c] -= f * R[(size_t)col*(HID+1)+c];
          }
        }
      }
      for (int r = HID - 1; r >= 0; r--) {
        double diag = M[(size_t)r * HID + r];
        for (int c = 0; c <= HID; c++) {
          double s = R[(size_t)r * (HID + 1) + c];
          for (int rr = r + 1; rr < HID; rr++) s -= M[(size_t)r*HID+rr] * X[(size_t)rr*(HID+1)+c];
          X[(size_t)r * (HID + 1) + c] = s / diag;
        }
      }
      // round to fp32 like the reference, iterate Krylov in double
      std::vector<double> Ad((size_t)HID * HID), h(HID), hn(HID);
      for (int r = 0; r < HID; r++) {
        for (int c = 0; c < HID; c++) Ad[(size_t)r*HID+c] = (double)(float)X[(size_t)r*(HID+1)+c];
        h[r] = (double)(float)X[(size_t)r*(HID+1)+HID];
      }
      for (int u = 0; u < T; u++) {
        for (int i = 0; i < HID; i++) h_H[(size_t)(uoff + u) * HID + i] = (float)h[i];
        for (int i = 0; i < HID; i++) {
          double s = 0; const double* row = &Ad[(size_t)i * HID];
          for (int j = 0; j < HID; j++) s += row[j] * h[j];
          hn[i] = s;
        }
        h.swap(hn);
      }
      // Legendre eval rows (last OLEN of T)
      for (int t = 0; t < OLEN; t++) {
        int j = T - OLEN + t;
        double x = 1.0 - 2.0 * ((double)j * dt);
        float* dst = &h_em[((size_t)si * OLEN + t) * HID];
        double p0 = 1.0, p1 = x;
        dst[0] = (float)p0; dst[1] = (float)p1;
        for (int n = 1; n < HID - 1; n++) {
          double p2 = ((2.0*n+1.0)*x*p1 - (double)n*p0) / (double)(n+1);
          dst[n+1] = (float)p2; p0 = p1; p1 = p2;
        }
      }
      // twiddles: w^j = e^{-2*pi*i*j/T}
      for (int j = 0; j < T; j++) {
        double th = PI2 * (double)j / (double)T;
        h_tw[(uoff + j) * 2 + 0] = (float)cos(th);
        h_tw[(uoff + j) * 2 + 1] = (float)(-sin(th));
      }
      // alpha_k = irfft-at-191 coefficient (positive exponent)
      h_al[(si * NMODE + 0) * 2 + 0] = (float)(1.0 / (double)T);
      h_al[(si * NMODE + 0) * 2 + 1] = 0.0f;
      for (int k = 1; k < NMODE; k++) {
        double th = PI2 * (double)(191 * k) / (double)T;
        h_al[(si * NMODE + k) * 2 + 0] = (float)(2.0 / T * cos(th));
        h_al[(si * NMODE + k) * 2 + 1] = (float)(2.0 / T * sin(th));
      }
    }
  }
};
static HostInit g_init;

// ---------------- device scratch ----------------
__device__ float d_W2[3 * 256 * 192 * 32 * 2];
__device__ float d_U[TSUM * NCOL];
__device__ float d_V[TSUM * NCOL];
__device__ float d_Cs[21 * 6144 * 2];
__device__ float d_Co[21 * 6144 * 2];
__device__ float d_G[TSUM * 192];
__device__ float d_Gc[768 * 192];
__device__ float d_Hd[TSUM * HID];
__device__ float d_emd[3 * 192 * 256];
__device__ float d_twd[TSUM * 2];
__device__ float d_ald[3 * 32 * 2];

// K0: pull host constants via ATS (GB300 C2C)
__global__ void k_copy(const float* __restrict__ hH, const float* __restrict__ hem,
                       const float* __restrict__ htw, const float* __restrict__ hal) {
  int i = blockIdx.x * blockDim.x + threadIdx.x, st = gridDim.x * blockDim.x;
  for (int j = i; j < TSUM * HID; j += st) d_Hd[j] = hH[j];
  for (int j = i; j < 3 * 192 * 256; j += st) d_emd[j] = hem[j];
  for (int j = i; j < TSUM * 2; j += st) d_twd[j] = htw[j];
  for (int j = i; j < 3 * 32 * 2; j += st) d_ald[j] = hal[j];
}

// K1: W2[s][i][t][k] = alpha_k * sum_o (wr+i*wi)[s,i,o,k] * em[s,t,o]
__global__ void k_w2(const float* __restrict__ wr, const float* __restrict__ wi) {
  __shared__ float em_s[32 * 196];
  __shared__ float ws_r[1024], ws_i[1024];
  int s = blockIdx.y, i = blockIdx.x;
  int tid = threadIdx.x, k = tid & 31, ty = tid >> 5;
  const float* emb = d_emd + s * 192 * 256;
  const float* wrb = wr + ((size_t)(s * 256 + i) * 256) * 32;
  const float* wib = wi + ((size_t)(s * 256 + i) * 256) * 32;
  float ar[24], ai[24];
#pragma unroll
  for (int j = 0; j < 24; j++) { ar[j] = 0.f; ai[j] = 0.f; }
  for (int oc = 0; oc < 256; oc += 32) {
    __syncthreads();
    for (int e = tid; e < 6144; e += 256) { int o = e & 31, t = e >> 5; em_s[o * 196 + t] = emb[t * 256 + oc + o]; }
    for (int e = tid; e < 1024; e += 256) { int o = e >> 5, kk = e & 31; ws_r[e] = wrb[(oc + o) * 32 + kk]; ws_i[e] = wib[(oc + o) * 32 + kk]; }
    __syncthreads();
#pragma unroll 4
    for (int o = 0; o < 32; o++) {
      float a = ws_r[o * 32 + k], b = ws_i[o * 32 + k];
      const float4* e4 = (const float4*)(em_s + o * 196 + ty * 24);
#pragma unroll
      for (int j = 0; j < 6; j++) {
        float4 e = e4[j];
        ar[j*4+0] += a*e.x; ai[j*4+0] += b*e.x;
        ar[j*4+1] += a*e.y; ai[j*4+1] += b*e.y;
        ar[j*4+2] += a*e.z; ai[j*4+2] += b*e.z;
        ar[j*4+3] += a*e.w; ai[j*4+3] += b*e.w;
      }
    }
  }
  float alr = d_ald[(s * 32 + k) * 2], ali = d_ald[(s * 32 + k) * 2 + 1];
  float2* outp = (float2*)d_W2 + (size_t)(s * 256 + i) * 192 * 32 + k;
#pragma unroll
  for (int j = 0; j < 24; j++) {
    int t = ty * 24 + j;
    outp[(size_t)t * 32] = make_float2(alr * ar[j] - ali * ai[j], alr * ai[j] + ali * ar[j]);
  }
}

// K2: U[u, n] = sum_i H[u,i] * W2[s(u)][i, n]   (SGEMM 64x64, 4x4 micro)
__global__ void k_gemmU() {
  __shared__ float As[16 * 68];
  __shared__ float Bs[16 * 64];
  int bn = blockIdx.x, bu = blockIdx.y;
  int u0 = bu * 64;
  int s = (u0 < 192) ? 0 : (u0 < 576) ? 1 : 2;
  const float* A = d_Hd + (size_t)u0 * 256;
  const float* B = d_W2 + (size_t)s * 256 * NCOL + bn * 64;
  float* C = d_U + (size_t)u0 * NCOL + bn * 64;
  int tid = threadIdx.x, tx = tid & 15, ty = tid >> 4;
  int ar_ = tid >> 2, ac = (tid & 3) * 4;
  int br_ = tid >> 4, bc = (tid & 15) * 4;
  float acc[4][4];
#pragma unroll
  for (int a = 0; a < 4; a++) for (int b = 0; b < 4; b++) acc[a][b] = 0.f;
  for (int kk = 0; kk < 256; kk += 16) {
    float4 av = *(const float4*)(A + ar_ * 256 + kk + ac);
    float4 bv = *(const float4*)(B + (size_t)(kk + br_) * NCOL + bc);
    __syncthreads();
    As[(ac + 0) * 68 + ar_] = av.x; As[(ac + 1) * 68 + ar_] = av.y;
    As[(ac + 2) * 68 + ar_] = av.z; As[(ac + 3) * 68 + ar_] = av.w;
    *(float4*)(Bs + br_ * 64 + bc) = bv;
    __syncthreads();
#pragma unroll
    for (int p = 0; p < 16; p++) {
      float4 a4 = *(const float4*)(As + p * 68 + ty * 4);
      float4 b4 = *(const float4*)(Bs + p * 64 + tx * 4);
      acc[0][0]+=a4.x*b4.x; acc[0][1]+=a4.x*b4.y; acc[0][2]+=a4.x*b4.z; acc[0][3]+=a4.x*b4.w;
      acc[1][0]+=a4.y*b4.x; acc[1][1]+=a4.y*b4.y; acc[1][2]+=a4.y*b4.z; acc[1][3]+=a4.y*b4.w;
      acc[2][0]+=a4.z*b4.x; acc[2][1]+=a4.z*b4.y; acc[2][2]+=a4.z*b4.z; acc[2][3]+=a4.z*b4.w;
      acc[3][0]+=a4.w*b4.x; acc[3][1]+=a4.w*b4.y; acc[3][2]+=a4.w*b4.z; acc[3][3]+=a4.w*b4.w;
    }
  }
#pragma unroll
  for (int r = 0; r < 4; r++) {
    float4 v = make_float4(acc[r][0], acc[r][1], acc[r][2], acc[r][3]);
    *(float4*)(C + (size_t)(ty * 4 + r) * NCOL + tx * 4) = v;
  }
}

// K3a: twiddle-multiply + chunk-local (64) inclusive prefix over u
__global__ void k_scan() {
  int tk = blockIdx.x * 256 + threadIdx.x;
  int cg = blockIdx.y;
  int s, coff;
  if (cg < 3) { s = 0; coff = 0; } else if (cg < 9) { s = 1; coff = 3; } else { s = 2; coff = 9; }
  int T = 192 << s;
  int uoff = (s == 0) ? 0 : (s == 1) ? 192 : 576;
  int u0 = (cg - coff) * 64, k = tk & 31;
  int j = (u0 * k) % T;
  const float2* tw = (const float2*)d_twd + uoff;
  const float2* Up = (const float2*)d_U + (size_t)(uoff + u0) * 6144 + tk;
  float2* Vp = (float2*)d_V + (size_t)(uoff + u0) * 6144 + tk;
  float2 run = make_float2(0.f, 0.f);
  for (int u = 0; u < 64; u++) {
    float2 x = Up[(size_t)u * 6144];
    float2 w = tw[j];
    run.x += w.x * x.x - w.y * x.y;
    run.y += w.x * x.y + w.y * x.x;
    Vp[(size_t)u * 6144] = run;
    j += k; if (j >= T) j -= T;
  }
  ((float2*)d_Cs)[cg * 6144 + tk] = run;
}

// K3b: exclusive scan of chunk sums within each scale
__global__ void k_coff() {
  int idx = blockIdx.x * 256 + threadIdx.x;
  if (idx >= 21 * 6144) return;
  int cg = idx / 6144, tk = idx % 6144;
  int c0 = (cg < 3) ? 0 : (cg < 9) ? 3 : 9;
  float2 sum = make_float2(0.f, 0.f);
  for (int c = c0; c < cg; c++) { float2 v = ((float2*)d_Cs)[c * 6144 + tk]; sum.x += v.x; sum.y += v.y; }
  ((float2*)d_Co)[cg * 6144 + tk] = sum;
}

// K4: G[taug, t] = sum_k Re(w^{tau*k} * Vfull[T-1-tau, t, k]) via warp reduce
__global__ void k_G() {
  int gw = (blockIdx.x * 256 + threadIdx.x) >> 5;
  int lane = threadIdx.x & 31;
  if (gw >= TSUM * 192) return;
  int tg = gw / 192, t = gw % 192;
  int s = (tg < 192) ? 0 : (tg < 576) ? 1 : 2;
  int uoff = (s == 0) ? 0 : (s == 1) ? 192 : 576;
  int T = 192 << s;
  int tau = tg - uoff, m = T - 1 - tau;
  int cg = ((s == 0) ? 0 : (s == 1) ? 3 : 9) + (m >> 6);
  float2 v = ((const float2*)d_V)[(size_t)(uoff + m) * 6144 + t * 32 + lane];
  float2 o = ((const float2*)d_Co)[cg * 6144 + t * 32 + lane];
  v.x += o.x; v.y += o.y;
  int j = (tau * lane) % T;
  float2 w = ((const float2*)d_twd)[uoff + j];
  float p = w.x * v.x - w.y * v.y;
#pragma unroll
  for (int off = 16; off; off >>= 1) p += __shfl_xor_sync(0xffffffffu, p, off);
  if (!lane) d_G[(size_t)tg * 192 + t] = p;
}

// K5: combine scales with mlp weights into one [768 x 192] kernel matrix
__global__ void k_comb(const float* __restrict__ mw) {
  int idx = blockIdx.x * 256 + threadIdx.x;
  if (idx >= 768 * 192) return;
  int jj = idx / 192, t = idx % 192;
  float acc = mw[2] * d_G[(size_t)(576 + jj) * 192 + t];
  if (jj >= 384) acc += mw[1] * d_G[(size_t)(192 + jj - 384) * 192 + t];
  if (jj >= 576) acc += mw[0] * d_G[(size_t)(jj - 576) * 192 + t];
  d_Gc[idx] = acc;
}

// K6: out[b,t,d] = mlp_b + sum_j inputs[b,j,d] * Gc[j,t]
__global__ void k_out(const float* __restrict__ inp, const float* __restrict__ mb, float* __restrict__ out) {
  __shared__ float fs[4096];
  int b = blockIdx.y, tt = blockIdx.x;
  int tid = threadIdx.x, d = tid & 63, tq = tid >> 6;
  float acc[4] = {0.f, 0.f, 0.f, 0.f};
  const float* ib = inp + (size_t)b * 768 * 64;
  for (int j0 = 0; j0 < 768; j0 += 64) {
    __syncthreads();
    for (int e = tid; e < 4096; e += 256) fs[e] = ib[(size_t)j0 * 64 + e];
    __syncthreads();
    for (int jj = 0; jj < 64; jj++) {
      float f = fs[jj * 64 + d];
#pragma unroll
      for (int l = 0; l < 4; l++) {
        int t = tt * 16 + tq * 4 + l;
        acc[l] += f * d_Gc[(size_t)(j0 + jj) * 192 + t];
      }
    }
  }
  float bb = mb[0];
#pragma unroll
  for (int l = 0; l < 4; l++) {
    int t = tt * 16 + tq * 4 + l;
    out[((size_t)b * 192 + t) * 64 + d] = acc[l] + bb;
  }
}

extern "C" void kernel_launch(void* const* d_in, const int* in_sizes, int n_in,
                              void* d_out, int out_size) {
  const float* inputs = (const float*)d_in[0];
  const float* spec_wr = (const float*)d_in[1];
  const float* spec_wi = (const float*)d_in[2];
  const float* mlp_w = (const float*)d_in[3];
  const float* mlp_b = (const float*)d_in[4];
  float* out = (float*)d_out;

  k_copy<<<256, 256>>>(h_H, h_em, h_tw, h_al);
  k_w2<<<dim3(256, 3), 256>>>(spec_wr, spec_wi);
  k_gemmU<<<dim3(192, 21), 256>>>();
  k_scan<<<dim3(24, 21), 256>>>();
  k_coff<<<(21 * 6144 + 255) / 256, 256>>>();
  k_G<<<(TSUM * 192 * 32 + 255) / 256, 256>>>();
  k_comb<<<(768 * 192 + 255) / 256, 256>>>(mlp_w);
  k_out<<<dim3(12, 8), 256>>>(inputs, mlp_b, out);
}

// round 4
// speedup vs baseline: 1.0072x; 1.0072x over previous
#include <cuda_runtime.h>
#include <vector>
#include <cmath>

#define HID 256
#define OLEN 192
#define NMODE 32
#define TSUM 1344
#define NCOL 12288   // 192*32*2

// ---------------- host constant tables ----------------
static float h_H[TSUM * HID];
static float h_em[3 * OLEN * HID];
static float h_tw[TSUM * 2];
static float h_al[3 * NMODE * 2];

struct HostInit {
  HostInit() {
    const double PI2 = 6.283185307179586476925286766559;
    for (int si = 0; si < 3; si++) {
      int sc = 1 << si;
      int T = OLEN * sc;
      int uoff = (si == 0) ? 0 : (si == 1) ? 192 : 576;
      double dt = 1.0 / (double)T;
      std::vector<double> M((size_t)HID * HID), R((size_t)HID * (HID + 1)), X((size_t)HID * (HID + 1));
      for (int r = 0; r < HID; r++) {
        for (int c = 0; c < HID; c++) {
          double a = (r < c) ? -1.0 : (((r - c) & 1) ? 1.0 : -1.0);
          a *= (2.0 * r + 1.0);
          M[(size_t)r * HID + c] = (r == c ? 1.0 : 0.0) - 0.5 * dt * a;
          R[(size_t)r * (HID + 1) + c] = (r == c ? 1.0 : 0.0) + 0.5 * dt * a;
        }
        R[(size_t)r * (HID + 1) + HID] = ((r & 1) ? -1.0 : 1.0) * (2.0 * r + 1.0) * dt;
      }
      for (int col = 0; col < HID; col++) {
        int piv = col; double mx = fabs(M[(size_t)col * HID + col]);
        for (int r = col + 1; r < HID; r++) { double v = fabs(M[(size_t)r * HID + col]); if (v > mx) { mx = v; piv = r; } }
        if (piv != col) {
          for (int c = col; c < HID; c++) { double t = M[(size_t)col*HID+c]; M[(size_t)col*HID+c] = M[(size_t)piv*HID+c]; M[(size_t)piv*HID+c] = t; }
          for (int c = 0; c <= HID; c++) { double t = R[(size_t)col*(HID+1)+c]; R[(size_t)col*(HID+1)+c] = R[(size_t)piv*(HID+1)+c]; R[(size_t)piv*(HID+1)+c] = t; }
        }
        double d = M[(size_t)col * HID + col];
        for (int r = col + 1; r < HID; r++) {
          double f = M[(size_t)r * HID + col] / d;
          if (f != 0.0) {
            for (int c = col; c < HID; c++) M[(size_t)r*HID+c] -= f * M[(size_t)col*HID+c];
            for (int c = 0; c <= HID; c++) R[(size_t)r*(HID+1)+c] -= f * R[(size_t)col*(HID+1)+c];
          }
        }
      }
      for (int r = HID - 1; r >= 0; r--) {
        double diag = M[(size_t)r * HID + r];
        for (int c = 0; c <= HID; c++) {
          double s = R[(size_t)r * (HID + 1) + c];
          for (int rr = r + 1; rr < HID; rr++) s -= M[(size_t)r*HID+rr] * X[(size_t)rr*(HID+1)+c];
          X[(size_t)r * (HID + 1) + c] = s / diag;
        }
      }
      std::vector<double> Ad((size_t)HID * HID), h(HID), hn(HID);
      for (int r = 0; r < HID; r++) {
        for (int c = 0; c < HID; c++) Ad[(size_t)r*HID+c] = (double)(float)X[(size_t)r*(HID+1)+c];
        h[r] = (double)(float)X[(size_t)r*(HID+1)+HID];
      }
      for (int u = 0; u < T; u++) {
        for (int i = 0; i < HID; i++) h_H[(size_t)(uoff + u) * HID + i] = (float)h[i];
        for (int i = 0; i < HID; i++) {
          double s = 0; const double* row = &Ad[(size_t)i * HID];
          for (int j = 0; j < HID; j++) s += row[j] * h[j];
          hn[i] = s;
        }
        h.swap(hn);
      }
      for (int t = 0; t < OLEN; t++) {
        int j = T - OLEN + t;
        double x = 1.0 - 2.0 * ((double)j * dt);
        float* dst = &h_em[((size_t)si * OLEN + t) * HID];
        double p0 = 1.0, p1 = x;
        dst[0] = (float)p0; dst[1] = (float)p1;
        for (int n = 1; n < HID - 1; n++) {
          double p2 = ((2.0*n+1.0)*x*p1 - (double)n*p0) / (double)(n+1);
          dst[n+1] = (float)p2; p0 = p1; p1 = p2;
        }
      }
      for (int j = 0; j < T; j++) {
        double th = PI2 * (double)j / (double)T;
        h_tw[(uoff + j) * 2 + 0] = (float)cos(th);
        h_tw[(uoff + j) * 2 + 1] = (float)(-sin(th));
      }
      h_al[(si * NMODE + 0) * 2 + 0] = (float)(1.0 / (double)T);
      h_al[(si * NMODE + 0) * 2 + 1] = 0.0f;
      for (int k = 1; k < NMODE; k++) {
        double th = PI2 * (double)(191 * k) / (double)T;
        h_al[(si * NMODE + k) * 2 + 0] = (float)(2.0 / T * cos(th));
        h_al[(si * NMODE + k) * 2 + 1] = (float)(2.0 / T * sin(th));
      }
    }
  }
};
static HostInit g_init;

// ---------------- device scratch ----------------
__device__ float d_W2[3 * 256 * 192 * 32 * 2];
__device__ float d_U[TSUM * NCOL];
__device__ float d_Cs[21 * 6144 * 2];
__device__ float d_Co[21 * 6144 * 2];
__device__ float d_G[TSUM * 192];
__device__ float d_Gc[768 * 192];
__device__ float d_Hd[TSUM * HID];
__device__ float d_emd[3 * 192 * 256];
__device__ float d_twd[TSUM * 2];
__device__ float d_ald[3 * 32 * 2];

// packed f32x2 helpers (Blackwell)
__device__ __forceinline__ unsigned long long pack2(float x) {
  unsigned long long r; asm("mov.b64 %0, {%1, %1};" : "=l"(r) : "f"(x)); return r;
}
#define FMA2(d, a, b) asm("fma.rn.f32x2 %0, %1, %2, %0;" : "+l"(d) : "l"(a), "l"(b))
union U2 { unsigned long long u; float2 f; };

// K0: pull host constants via ATS (GB300 C2C)
__global__ void k_copy(const float* __restrict__ hH, const float* __restrict__ hem,
                       const float* __restrict__ htw, const float* __restrict__ hal) {
  int i = blockIdx.x * blockDim.x + threadIdx.x, st = gridDim.x * blockDim.x;
  for (int j = i; j < TSUM * HID; j += st) d_Hd[j] = hH[j];
  for (int j = i; j < 3 * 192 * 256; j += st) d_emd[j] = hem[j];
  for (int j = i; j < TSUM * 2; j += st) d_twd[j] = htw[j];
  for (int j = i; j < 3 * 32 * 2; j += st) d_ald[j] = hal[j];
}

// K1: W2[s][i][t][k] = alpha_k * sum_o (wr+i*wi)[s,i,o,k] * em[s,t,o]  (f32x2)
__global__ void k_w2(const float* __restrict__ wr, const float* __restrict__ wi) {
  __shared__ float em_s[32 * 196];
  __shared__ float ws_r[1024], ws_i[1024];
  int s = blockIdx.y, i = blockIdx.x;
  int tid = threadIdx.x, k = tid & 31, ty = tid >> 5;
  const float* emb = d_emd + s * 192 * 256;
  const float* wrb = wr + ((size_t)(s * 256 + i) * 256) * 32;
  const float* wib = wi + ((size_t)(s * 256 + i) * 256) * 32;
  unsigned long long ar2[12], ai2[12];
#pragma unroll
  for (int j = 0; j < 12; j++) { ar2[j] = 0ull; ai2[j] = 0ull; }
  for (int oc = 0; oc < 256; oc += 32) {
    __syncthreads();
    for (int e = tid; e < 6144; e += 256) { int o = e & 31, t = e >> 5; em_s[o * 196 + t] = emb[t * 256 + oc + o]; }
    for (int e = tid; e < 1024; e += 256) { int o = e >> 5, kk = e & 31; ws_r[e] = wrb[(oc + o) * 32 + kk]; ws_i[e] = wib[(oc + o) * 32 + kk]; }
    __syncthreads();
#pragma unroll 4
    for (int o = 0; o < 32; o++) {
      unsigned long long aa = pack2(ws_r[o * 32 + k]);
      unsigned long long bb = pack2(ws_i[o * 32 + k]);
      const unsigned long long* e2 = (const unsigned long long*)(em_s + o * 196 + ty * 24);
#pragma unroll
      for (int j = 0; j < 12; j++) {
        unsigned long long ev = e2[j];
        FMA2(ar2[j], aa, ev);
        FMA2(ai2[j], bb, ev);
      }
    }
  }
  float alr = d_ald[(s * 32 + k) * 2], ali = d_ald[(s * 32 + k) * 2 + 1];
  float2* outp = (float2*)d_W2 + (size_t)(s * 256 + i) * 192 * 32 + k;
#pragma unroll
  for (int j = 0; j < 12; j++) {
    U2 xr, xi; xr.u = ar2[j]; xi.u = ai2[j];
    int t0 = ty * 24 + 2 * j;
    outp[(size_t)t0 * 32]       = make_float2(alr * xr.f.x - ali * xi.f.x, alr * xi.f.x + ali * xr.f.x);
    outp[(size_t)(t0 + 1) * 32] = make_float2(alr * xr.f.y - ali * xi.f.y, alr * xi.f.y + ali * xr.f.y);
  }
}

// K2: U[u, n] = sum_i H[u,i] * W2[s(u)][i, n]   (SGEMM 64x128, 4x8 micro, f32x2)
__global__ void k_gemmU() {
  __shared__ float As[16 * 68];
  __shared__ float Bs[16 * 128];
  int bn = blockIdx.x, bu = blockIdx.y;
  int u0 = bu * 64;
  int s = (u0 < 192) ? 0 : (u0 < 576) ? 1 : 2;
  const float* A = d_Hd + (size_t)u0 * 256;
  const float* B = d_W2 + (size_t)s * 256 * NCOL + bn * 128;
  float* C = d_U + (size_t)u0 * NCOL + bn * 128;
  int tid = threadIdx.x, tx = tid & 15, ty = tid >> 4;
  int ar_ = tid >> 2, ac = (tid & 3) * 4;
  int br_ = tid >> 4, bc8 = (tid & 15) * 8;
  unsigned long long acc[4][4];
#pragma unroll
  for (int a = 0; a < 4; a++)
#pragma unroll
    for (int b = 0; b < 4; b++) acc[a][b] = 0ull;
  for (int kk = 0; kk < 256; kk += 16) {
    float4 av  = *(const float4*)(A + (size_t)ar_ * 256 + kk + ac);
    float4 bv0 = *(const float4*)(B + (size_t)(kk + br_) * NCOL + bc8);
    float4 bv1 = *(const float4*)(B + (size_t)(kk + br_) * NCOL + bc8 + 4);
    __syncthreads();
    As[(ac + 0) * 68 + ar_] = av.x; As[(ac + 1) * 68 + ar_] = av.y;
    As[(ac + 2) * 68 + ar_] = av.z; As[(ac + 3) * 68 + ar_] = av.w;
    *(float4*)(Bs + br_ * 128 + bc8) = bv0;
    *(float4*)(Bs + br_ * 128 + bc8 + 4) = bv1;
    __syncthreads();
#pragma unroll
    for (int p = 0; p < 16; p++) {
      float4 a4 = *(const float4*)(As + p * 68 + ty * 4);
      ulonglong2 bA = *(const ulonglong2*)(Bs + p * 128 + tx * 8);
      ulonglong2 bB = *(const ulonglong2*)(Bs + p * 128 + tx * 8 + 4);
      unsigned long long aa;
      aa = pack2(a4.x);
      FMA2(acc[0][0], aa, bA.x); FMA2(acc[0][1], aa, bA.y);
      FMA2(acc[0][2], aa, bB.x); FMA2(acc[0][3], aa, bB.y);
      aa = pack2(a4.y);
      FMA2(acc[1][0], aa, bA.x); FMA2(acc[1][1], aa, bA.y);
      FMA2(acc[1][2], aa, bB.x); FMA2(acc[1][3], aa, bB.y);
      aa = pack2(a4.z);
      FMA2(acc[2][0], aa, bA.x); FMA2(acc[2][1], aa, bA.y);
      FMA2(acc[2][2], aa, bB.x); FMA2(acc[2][3], aa, bB.y);
      aa = pack2(a4.w);
      FMA2(acc[3][0], aa, bA.x); FMA2(acc[3][1], aa, bA.y);
      FMA2(acc[3][2], aa, bB.x); FMA2(acc[3][3], aa, bB.y);
    }
  }
#pragma unroll
  for (int r = 0; r < 4; r++) {
    float* cp = C + (size_t)(ty * 4 + r) * NCOL + tx * 8;
    *(ulonglong2*)cp       = make_ulonglong2(acc[r][0], acc[r][1]);
    *(ulonglong2*)(cp + 4) = make_ulonglong2(acc[r][2], acc[r][3]);
  }
}

// K3a: per-chunk (64 u) twiddled sums only (no V materialization)
__global__ void k_chunksum() {
  int tk = blockIdx.x * 256 + threadIdx.x;
  int cg = blockIdx.y;
  int s, coff;
  if (cg < 3) { s = 0; coff = 0; } else if (cg < 9) { s = 1; coff = 3; } else { s = 2; coff = 9; }
  int T = 192 << s;
  int uoff = (s == 0) ? 0 : (s == 1) ? 192 : 576;
  int u0 = (cg - coff) * 64, k = tk & 31;
  int j = (u0 * k) % T;
  const float2* tw = (const float2*)d_twd + uoff;
  const float2* Up = (const float2*)d_U + (size_t)(uoff + u0) * 6144 + tk;
  float2 run = make_float2(0.f, 0.f);
  for (int u = 0; u < 64; u++) {
    float2 x = Up[(size_t)u * 6144];
    float2 w = tw[j];
    run.x += w.x * x.x - w.y * x.y;
    run.y += w.x * x.y + w.y * x.x;
    j += k; if (j >= T) j -= T;
  }
  ((float2*)d_Cs)[cg * 6144 + tk] = run;
}

// K3b: exclusive scan of chunk sums within each scale
__global__ void k_coff() {
  int idx = blockIdx.x * 256 + threadIdx.x;
  if (idx >= 21 * 6144) return;
  int cg = idx / 6144, tk = idx % 6144;
  int c0 = (cg < 3) ? 0 : (cg < 9) ? 3 : 9;
  float2 sum = make_float2(0.f, 0.f);
  for (int c = c0; c < cg; c++) { float2 v = ((float2*)d_Cs)[c * 6144 + tk]; sum.x += v.x; sum.y += v.y; }
  ((float2*)d_Co)[cg * 6144 + tk] = sum;
}

// K3c: recompute running prefix (seeded with chunk offset) and reduce into G
// G[uoff+tau, t] = sum_k Re(tw[tau*k] * V[T-1-tau, t, k]),  warp lane = k
__global__ void k_scanG() {
  int tk = blockIdx.x * 256 + threadIdx.x;
  int cg = blockIdx.y;
  int s, coff;
  if (cg < 3) { s = 0; coff = 0; } else if (cg < 9) { s = 1; coff = 3; } else { s = 2; coff = 9; }
  int T = 192 << s;
  int uoff = (s == 0) ? 0 : (s == 1) ? 192 : 576;
  int u0 = (cg - coff) * 64;
  int k = tk & 31, t = tk >> 5, lane = threadIdx.x & 31;
  int j = (u0 * k) % T;
  int tau0 = T - 1 - u0;
  int j2 = (tau0 * k) % T;
  const float2* tw = (const float2*)d_twd + uoff;
  const float2* Up = (const float2*)d_U + (size_t)(uoff + u0) * 6144 + tk;
  float2 run = ((const float2*)d_Co)[cg * 6144 + tk];
  for (int u = 0; u < 64; u++) {
    float2 x = Up[(size_t)u * 6144];
    float2 w = tw[j];
    run.x += w.x * x.x - w.y * x.y;
    run.y += w.x * x.y + w.y * x.x;
    float2 w2 = tw[j2];
    float p = w2.x * run.x - w2.y * run.y;
#pragma unroll
    for (int off = 16; off; off >>= 1) p += __shfl_xor_sync(0xffffffffu, p, off);
    if (!lane) d_G[(size_t)(uoff + tau0 - u) * 192 + t] = p;
    j += k; if (j >= T) j -= T;
    j2 -= k; if (j2 < 0) j2 += T;
  }
}

// K5: combine scales with mlp weights into one [768 x 192] kernel matrix
__global__ void k_comb(const float* __restrict__ mw) {
  int idx = blockIdx.x * 256 + threadIdx.x;
  if (idx >= 768 * 192) return;
  int jj = idx / 192, t = idx % 192;
  float acc = mw[2] * d_G[(size_t)(576 + jj) * 192 + t];
  if (jj >= 384) acc += mw[1] * d_G[(size_t)(192 + jj - 384) * 192 + t];
  if (jj >= 576) acc += mw[0] * d_G[(size_t)(jj - 576) * 192 + t];
  d_Gc[idx] = acc;
}

// K6: out[b,t,d] = mlp_b + sum_j inputs[b,j,d] * Gc[j,t]
__global__ void k_out(const float* __restrict__ inp, const float* __restrict__ mb, float* __restrict__ out) {
  __shared__ float fs[4096];
  int b = blockIdx.y, tt = blockIdx.x;
  int tid = threadIdx.x, d = tid & 63, tq = tid >> 6;
  float acc[4] = {0.f, 0.f, 0.f, 0.f};
  const float* ib = inp + (size_t)b * 768 * 64;
  for (int j0 = 0; j0 < 768; j0 += 64) {
    __syncthreads();
    for (int e = tid; e < 4096; e += 256) fs[e] = ib[(size_t)j0 * 64 + e];
    __syncthreads();
    for (int jj = 0; jj < 64; jj++) {
      float f = fs[jj * 64 + d];
#pragma unroll
      for (int l = 0; l < 4; l++) {
        int t = tt * 16 + tq * 4 + l;
        acc[l] += f * d_Gc[(size_t)(j0 + jj) * 192 + t];
      }
    }
  }
  float bb = mb[0];
#pragma unroll
  for (int l = 0; l < 4; l++) {
    int t = tt * 16 + tq * 4 + l;
    out[((size_t)b * 192 + t) * 64 + d] = acc[l] + bb;
  }
}

extern "C" void kernel_launch(void* const* d_in, const int* in_sizes, int n_in,
                              void* d_out, int out_size) {
  const float* inputs = (const float*)d_in[0];
  const float* spec_wr = (const float*)d_in[1];
  const float* spec_wi = (const float*)d_in[2];
  const float* mlp_w = (const float*)d_in[3];
  const float* mlp_b = (const float*)d_in[4];
  float* out = (float*)d_out;

  k_copy<<<256, 256>>>(h_H, h_em, h_tw, h_al);
  k_w2<<<dim3(256, 3), 256>>>(spec_wr, spec_wi);
  k_gemmU<<<dim3(96, 21), 256>>>();
  k_chunksum<<<dim3(24, 21), 256>>>();
  k_coff<<<(21 * 6144 + 255) / 256, 256>>>();
  k_scanG<<<dim3(24, 21), 256>>>();
  k_comb<<<(768 * 192 + 255) / 256, 256>>>(mlp_w);
  k_out<<<dim3(12, 8), 256>>>(inputs, mlp_b, out);
}

// round 5
// speedup vs baseline: 1.1930x; 1.1845x over previous
#include <cuda_runtime.h>
#include <vector>
#include <cmath>

#define HID 256
#define OLEN 192
#define NMODE 32
#define TSUM 1344
#define NCOL 12288   // 192*32*2

// ---------------- host constant tables ----------------
static float h_H[TSUM * HID];
static float h_em[3 * OLEN * HID];
static float h_tw[TSUM * 2];
static float h_al[3 * NMODE * 2];

struct HostInit {
  HostInit() {
    const double PI2 = 6.283185307179586476925286766559;
    for (int si = 0; si < 3; si++) {
      int sc = 1 << si;
      int T = OLEN * sc;
      int uoff = (si == 0) ? 0 : (si == 1) ? 192 : 576;
      double dt = 1.0 / (double)T;
      std::vector<double> M((size_t)HID * HID), R((size_t)HID * (HID + 1)), X((size_t)HID * (HID + 1));
      for (int r = 0; r < HID; r++) {
        for (int c = 0; c < HID; c++) {
          double a = (r < c) ? -1.0 : (((r - c) & 1) ? 1.0 : -1.0);
          a *= (2.0 * r + 1.0);
          M[(size_t)r * HID + c] = (r == c ? 1.0 : 0.0) - 0.5 * dt * a;
          R[(size_t)r * (HID + 1) + c] = (r == c ? 1.0 : 0.0) + 0.5 * dt * a;
        }
        R[(size_t)r * (HID + 1) + HID] = ((r & 1) ? -1.0 : 1.0) * (2.0 * r + 1.0) * dt;
      }
      for (int col = 0; col < HID; col++) {
        int piv = col; double mx = fabs(M[(size_t)col * HID + col]);
        for (int r = col + 1; r < HID; r++) { double v = fabs(M[(size_t)r * HID + col]); if (v > mx) { mx = v; piv = r; } }
        if (piv != col) {
          for (int c = col; c < HID; c++) { double t = M[(size_t)col*HID+c]; M[(size_t)col*HID+c] = M[(size_t)piv*HID+c]; M[(size_t)piv*HID+c] = t; }
          for (int c = 0; c <= HID; c++) { double t = R[(size_t)col*(HID+1)+c]; R[(size_t)col*(HID+1)+c] = R[(size_t)piv*(HID+1)+c]; R[(size_t)piv*(HID+1)+c] = t; }
        }
        double d = M[(size_t)col * HID + col];
        for (int r = col + 1; r < HID; r++) {
          double f = M[(size_t)r * HID + col] / d;
          if (f != 0.0) {
            for (int c = col; c < HID; c++) M[(size_t)r*HID+c] -= f * M[(size_t)col*HID+c];
            for (int c = 0; c <= HID; c++) R[(size_t)r*(HID+1)+c] -= f * R[(size_t)col*(HID+1)+c];
          }
        }
      }
      for (int r = HID - 1; r >= 0; r--) {
        double diag = M[(size_t)r * HID + r];
        for (int c = 0; c <= HID; c++) {
          double s = R[(size_t)r * (HID + 1) + c];
          for (int rr = r + 1; rr < HID; rr++) s -= M[(size_t)r*HID+rr] * X[(size_t)rr*(HID+1)+c];
          X[(size_t)r * (HID + 1) + c] = s / diag;
        }
      }
      std::vector<double> Ad((size_t)HID * HID), h(HID), hn(HID);
      for (int r = 0; r < HID; r++) {
        for (int c = 0; c < HID; c++) Ad[(size_t)r*HID+c] = (double)(float)X[(size_t)r*(HID+1)+c];
        h[r] = (double)(float)X[(size_t)r*(HID+1)+HID];
      }
      for (int u = 0; u < T; u++) {
        for (int i = 0; i < HID; i++) h_H[(size_t)(uoff + u) * HID + i] = (float)h[i];
        for (int i = 0; i < HID; i++) {
          double s = 0; const double* row = &Ad[(size_t)i * HID];
          for (int j = 0; j < HID; j++) s += row[j] * h[j];
          hn[i] = s;
        }
        h.swap(hn);
      }
      for (int t = 0; t < OLEN; t++) {
        int j = T - OLEN + t;
        double x = 1.0 - 2.0 * ((double)j * dt);
        float* dst = &h_em[((size_t)si * OLEN + t) * HID];
        double p0 = 1.0, p1 = x;
        dst[0] = (float)p0; dst[1] = (float)p1;
        for (int n = 1; n < HID - 1; n++) {
          double p2 = ((2.0*n+1.0)*x*p1 - (double)n*p0) / (double)(n+1);
          dst[n+1] = (float)p2; p0 = p1; p1 = p2;
        }
      }
      for (int j = 0; j < T; j++) {
        double th = PI2 * (double)j / (double)T;
        h_tw[(uoff + j) * 2 + 0] = (float)cos(th);
        h_tw[(uoff + j) * 2 + 1] = (float)(-sin(th));
      }
      h_al[(si * NMODE + 0) * 2 + 0] = (float)(1.0 / (double)T);
      h_al[(si * NMODE + 0) * 2 + 1] = 0.0f;
      for (int k = 1; k < NMODE; k++) {
        double th = PI2 * (double)(191 * k) / (double)T;
        h_al[(si * NMODE + k) * 2 + 0] = (float)(2.0 / T * cos(th));
        h_al[(si * NMODE + k) * 2 + 1] = (float)(2.0 / T * sin(th));
      }
    }
  }
};
static HostInit g_init;

// ---------------- device scratch ----------------
__device__ float d_W2[3 * 256 * NCOL];
__device__ float d_U[TSUM * NCOL];
__device__ float d_Cs[21 * 6144 * 2];
__device__ float d_Co[21 * 6144 * 2];
__device__ float d_G[TSUM * 192];
__device__ float d_Gc[768 * 192];
__device__ float d_Hd[TSUM * HID];
__device__ float d_emd[3 * 192 * 256];
__device__ float d_twd[TSUM * 2];
__device__ float d_ald[3 * 32 * 2];

// ---------------- tf32 helpers ----------------
__device__ __forceinline__ float tf32_rna(float x) {
  unsigned u; asm("cvt.rna.tf32.f32 %0, %1;" : "=r"(u) : "f"(x)); return __uint_as_float(u);
}
__device__ __forceinline__ void mma8(float4& d, unsigned a0, unsigned a1, unsigned a2, unsigned a3,
                                     unsigned b0, unsigned b1) {
  asm("mma.sync.aligned.m16n8k8.row.col.f32.tf32.tf32.f32 "
      "{%0,%1,%2,%3}, {%4,%5,%6,%7}, {%8,%9}, {%0,%1,%2,%3};"
      : "+f"(d.x), "+f"(d.y), "+f"(d.z), "+f"(d.w)
      : "r"(a0), "r"(a1), "r"(a2), "r"(a3), "r"(b0), "r"(b1));
}
__device__ __forceinline__ unsigned f2u(float x) { return __float_as_uint(x); }

// K0: pull host constants via ATS (GB300 C2C)
__global__ void k_copy(const float* __restrict__ hH, const float* __restrict__ hem,
                       const float* __restrict__ htw, const float* __restrict__ hal) {
  int i = blockIdx.x * blockDim.x + threadIdx.x, st = gridDim.x * blockDim.x;
  for (int j = i; j < TSUM * HID; j += st) d_Hd[j] = hH[j];
  for (int j = i; j < 3 * 192 * 256; j += st) d_emd[j] = hem[j];
  for (int j = i; j < TSUM * 2; j += st) d_twd[j] = htw[j];
  for (int j = i; j < 3 * 32 * 2; j += st) d_ald[j] = hal[j];
}

// K1 (tensor): W2[s][i][t][2k+reim] = alpha_k * sum_o w[s,i,o,k] * em[s,t,o]
// GEMM per block: C[192 x 64] = em[192 x 256] @ Wc[256 x 64], 3-term tf32 split.
__global__ void k_w2(const float* __restrict__ wr, const float* __restrict__ wi) {
  __shared__ float Bh[32][72], Bl[32][72];
  int s = blockIdx.y, i = blockIdx.x;
  int tid = threadIdx.x, wid = tid >> 5, lane = tid & 31;
  int wm = (wid >> 1) * 48, wn = (wid & 1) * 32;
  int r = lane >> 2, cc = lane & 3;
  const float* emb = d_emd + s * 192 * 256;
  const float* wrb = wr + (size_t)(s * 256 + i) * 256 * 32;
  const float* wib = wi + (size_t)(s * 256 + i) * 256 * 32;
  float4 acc[3][4];
#pragma unroll
  for (int mt = 0; mt < 3; mt++)
#pragma unroll
    for (int j = 0; j < 4; j++) acc[mt][j] = make_float4(0.f, 0.f, 0.f, 0.f);

  for (int kk = 0; kk < 256; kk += 32) {
    __syncthreads();
    {
      int row = tid >> 3, qd = tid & 7;
      float4 vr = *(const float4*)(wrb + (size_t)(kk + row) * 32 + qd * 4);
      float4 vi = *(const float4*)(wib + (size_t)(kk + row) * 32 + qd * 4);
      float vre[4] = {vr.x, vr.y, vr.z, vr.w};
      float vim[4] = {vi.x, vi.y, vi.z, vi.w};
#pragma unroll
      for (int e = 0; e < 4; e++) {
        int n0 = (qd * 4 + e) * 2;
        float h = tf32_rna(vre[e]); Bh[row][n0] = h; Bl[row][n0] = vre[e] - h;
        h = tf32_rna(vim[e]); Bh[row][n0 + 1] = h; Bl[row][n0 + 1] = vim[e] - h;
      }
    }
    __syncthreads();
#pragma unroll
    for (int q = 0; q < 4; q++) {
      // B frags for this warp's 4 n-tiles
      unsigned b0h[4], b1h[4], b0l[4], b1l[4];
#pragma unroll
      for (int j = 0; j < 4; j++) {
        int n = wn + j * 8 + r;
        b0h[j] = f2u(Bh[q * 8 + cc][n]);     b1h[j] = f2u(Bh[q * 8 + cc + 4][n]);
        b0l[j] = f2u(Bl[q * 8 + cc][n]);     b1l[j] = f2u(Bl[q * 8 + cc + 4][n]);
      }
#pragma unroll
      for (int mt = 0; mt < 3; mt++) {
        int row0 = wm + mt * 16 + r;
        int kb = kk + q * 8 + cc;
        float a0r = emb[(size_t)row0 * 256 + kb];
        float a1r = emb[(size_t)(row0 + 8) * 256 + kb];
        float a2r = emb[(size_t)row0 * 256 + kb + 4];
        float a3r = emb[(size_t)(row0 + 8) * 256 + kb + 4];
        float a0h = tf32_rna(a0r), a1h = tf32_rna(a1r), a2h = tf32_rna(a2r), a3h = tf32_rna(a3r);
        unsigned h0 = f2u(a0h), h1 = f2u(a1h), h2 = f2u(a2h), h3 = f2u(a3h);
        unsigned l0 = f2u(a0r - a0h), l1 = f2u(a1r - a1h), l2 = f2u(a2r - a2h), l3 = f2u(a3r - a3h);
#pragma unroll
        for (int j = 0; j < 4; j++) {
          mma8(acc[mt][j], h0, h1, h2, h3, b0h[j], b1h[j]);
          mma8(acc[mt][j], h0, h1, h2, h3, b0l[j], b1l[j]);
          mma8(acc[mt][j], l0, l1, l2, l3, b0h[j], b1h[j]);
        }
      }
    }
  }
  // epilogue: complex alpha scale, store f32
  float* outb = d_W2 + (size_t)(s * 256 + i) * NCOL;
#pragma unroll
  for (int mt = 0; mt < 3; mt++) {
#pragma unroll
    for (int j = 0; j < 4; j++) {
      int ncol = wn + j * 8 + 2 * cc;
      int kmode = ncol >> 1;
      float alr = d_ald[(s * 32 + kmode) * 2], ali = d_ald[(s * 32 + kmode) * 2 + 1];
      float4 c = acc[mt][j];
      int t0 = wm + mt * 16 + r;
      float2 lo = make_float2(alr * c.x - ali * c.y, alr * c.y + ali * c.x);
      float2 hi = make_float2(alr * c.z - ali * c.w, alr * c.w + ali * c.z);
      *(float2*)(outb + (size_t)t0 * 64 + ncol) = lo;
      *(float2*)(outb + (size_t)(t0 + 8) * 64 + ncol) = hi;
    }
  }
}

// K2 (tensor): U[u, n] = sum_i H[u,i] * W2[s(u)][i, n], 3-term tf32 split.
// Block tile 64(u) x 64(n), K=256 in chunks of 32. 4 warps, each 16(u) x 64(n).
__global__ void k_gemmU() {
  __shared__ float Bh[32][72], Bl[32][72];
  int bn = blockIdx.x, bu = blockIdx.y;
  int u0 = bu * 64;
  int s = (u0 < 192) ? 0 : (u0 < 576) ? 1 : 2;
  const float* A = d_Hd + (size_t)u0 * 256;
  const float* B = d_W2 + (size_t)s * 256 * NCOL + bn * 64;
  float* C = d_U + (size_t)u0 * NCOL + bn * 64;
  int tid = threadIdx.x, wid = tid >> 5, lane = tid & 31;
  int r = lane >> 2, cc = lane & 3;
  float4 acc[8];
#pragma unroll
  for (int j = 0; j < 8; j++) acc[j] = make_float4(0.f, 0.f, 0.f, 0.f);

  for (int kk = 0; kk < 256; kk += 32) {
    __syncthreads();
#pragma unroll
    for (int it = 0; it < 4; it++) {
      int idx = it * 128 + tid;
      int row = idx >> 4, qd = idx & 15;
      float4 v = *(const float4*)(B + (size_t)(kk + row) * NCOL + qd * 4);
      float vv[4] = {v.x, v.y, v.z, v.w};
#pragma unroll
      for (int e = 0; e < 4; e++) {
        float h = tf32_rna(vv[e]);
        Bh[row][qd * 4 + e] = h; Bl[row][qd * 4 + e] = vv[e] - h;
      }
    }
    __syncthreads();
#pragma unroll
    for (int q = 0; q < 4; q++) {
      int row0 = wid * 16 + r;
      int kb = kk + q * 8 + cc;
      float a0r = A[(size_t)row0 * 256 + kb];
      float a1r = A[(size_t)(row0 + 8) * 256 + kb];
      float a2r = A[(size_t)row0 * 256 + kb + 4];
      float a3r = A[(size_t)(row0 + 8) * 256 + kb + 4];
      float a0h = tf32_rna(a0r), a1h = tf32_rna(a1r), a2h = tf32_rna(a2r), a3h = tf32_rna(a3r);
      unsigned h0 = f2u(a0h), h1 = f2u(a1h), h2 = f2u(a2h), h3 = f2u(a3h);
      unsigned l0 = f2u(a0r - a0h), l1 = f2u(a1r - a1h), l2 = f2u(a2r - a2h), l3 = f2u(a3r - a3h);
#pragma unroll
      for (int j = 0; j < 8; j++) {
        int n = j * 8 + r;
        unsigned b0h = f2u(Bh[q * 8 + cc][n]), b1h = f2u(Bh[q * 8 + cc + 4][n]);
        unsigned b0l = f2u(Bl[q * 8 + cc][n]), b1l = f2u(Bl[q * 8 + cc + 4][n]);
        mma8(acc[j], h0, h1, h2, h3, b0h, b1h);
        mma8(acc[j], h0, h1, h2, h3, b0l, b1l);
        mma8(acc[j], l0, l1, l2, l3, b0h, b1h);
      }
    }
  }
#pragma unroll
  for (int j = 0; j < 8; j++) {
    float* cp = C + (size_t)(wid * 16 + r) * NCOL + j * 8 + 2 * cc;
    *(float2*)cp = make_float2(acc[j].x, acc[j].y);
    *(float2*)(cp + (size_t)8 * NCOL) = make_float2(acc[j].z, acc[j].w);
  }
}

// K3a: per-chunk (64 u) twiddled sums
__global__ void k_chunksum() {
  int tk = blockIdx.x * 256 + threadIdx.x;
  int cg = blockIdx.y;
  int s, coff;
  if (cg < 3) { s = 0; coff = 0; } else if (cg < 9) { s = 1; coff = 3; } else { s = 2; coff = 9; }
  int T = 192 << s;
  int uoff = (s == 0) ? 0 : (s == 1) ? 192 : 576;
  int u0 = (cg - coff) * 64, k = tk & 31;
  int j = (u0 * k) % T;
  const float2* tw = (const float2*)d_twd + uoff;
  const float2* Up = (const float2*)d_U + (size_t)(uoff + u0) * 6144 + tk;
  float2 run = make_float2(0.f, 0.f);
  for (int u = 0; u < 64; u++) {
    float2 x = Up[(size_t)u * 6144];
    float2 w = tw[j];
    run.x += w.x * x.x - w.y * x.y;
    run.y += w.x * x.y + w.y * x.x;
    j += k; if (j >= T) j -= T;
  }
  ((float2*)d_Cs)[cg * 6144 + tk] = run;
}

// K3b: exclusive scan of chunk sums within each scale
__global__ void k_coff() {
  int idx = blockIdx.x * 256 + threadIdx.x;
  if (idx >= 21 * 6144) return;
  int cg = idx / 6144, tk = idx % 6144;
  int c0 = (cg < 3) ? 0 : (cg < 9) ? 3 : 9;
  float2 sum = make_float2(0.f, 0.f);
  for (int c = c0; c < cg; c++) { float2 v = ((float2*)d_Cs)[c * 6144 + tk]; sum.x += v.x; sum.y += v.y; }
  ((float2*)d_Co)[cg * 6144 + tk] = sum;
}

// K3c: recompute running prefix (seeded) and reduce into G
__global__ void k_scanG() {
  int tk = blockIdx.x * 256 + threadIdx.x;
  int cg = blockIdx.y;
  int s, coff;
  if (cg < 3) { s = 0; coff = 0; } else if (cg < 9) { s = 1; coff = 3; } else { s = 2; coff = 9; }
  int T = 192 << s;
  int uoff = (s == 0) ? 0 : (s == 1) ? 192 : 576;
  int u0 = (cg - coff) * 64;
  int k = tk & 31, t = tk >> 5, lane = threadIdx.x & 31;
  int j = (u0 * k) % T;
  int tau0 = T - 1 - u0;
  int j2 = (tau0 * k) % T;
  const float2* tw = (const float2*)d_twd + uoff;
  const float2* Up = (const float2*)d_U + (size_t)(uoff + u0) * 6144 + tk;
  float2 run = ((const float2*)d_Co)[cg * 6144 + tk];
  for (int u = 0; u < 64; u++) {
    float2 x = Up[(size_t)u * 6144];
    float2 w = tw[j];
    run.x += w.x * x.x - w.y * x.y;
    run.y += w.x * x.y + w.y * x.x;
    float2 w2 = tw[j2];
    float p = w2.x * run.x - w2.y * run.y;
#pragma unroll
    for (int off = 16; off; off >>= 1) p += __shfl_xor_sync(0xffffffffu, p, off);
    if (!lane) d_G[(size_t)(uoff + tau0 - u) * 192 + t] = p;
    j += k; if (j >= T) j -= T;
    j2 -= k; if (j2 < 0) j2 += T;
  }
}

// K5: combine scales with mlp weights
__global__ void k_comb(const float* __restrict__ mw) {
  int idx = blockIdx.x * 256 + threadIdx.x;
  if (idx >= 768 * 192) return;
  int jj = idx / 192, t = idx % 192;
  float acc = mw[2] * d_G[(size_t)(576 + jj) * 192 + t];
  if (jj >= 384) acc += mw[1] * d_G[(size_t)(192 + jj - 384) * 192 + t];
  if (jj >= 576) acc += mw[0] * d_G[(size_t)(jj - 576) * 192 + t];
  d_Gc[idx] = acc;
}

// K6: out[b,t,d] = mlp_b + sum_j inputs[b,j,d] * Gc[j,t]
__global__ void k_out(const float* __restrict__ inp, const float* __restrict__ mb, float* __restrict__ out) {
  __shared__ float fs[4096];
  int b = blockIdx.y, tt = blockIdx.x;
  int tid = threadIdx.x, d = tid & 63, tq = tid >> 6;
  float acc[4] = {0.f, 0.f, 0.f, 0.f};
  const float* ib = inp + (size_t)b * 768 * 64;
  for (int j0 = 0; j0 < 768; j0 += 64) {
    __syncthreads();
    for (int e = tid; e < 4096; e += 256) fs[e] = ib[(size_t)j0 * 64 + e];
    __syncthreads();
    for (int jj = 0; jj < 64; jj++) {
      float f = fs[jj * 64 + d];
#pragma unroll
      for (int l = 0; l < 4; l++) {
        int t = tt * 16 + tq * 4 + l;
        acc[l] += f * d_Gc[(size_t)(j0 + jj) * 192 + t];
      }
    }
  }
  float bb = mb[0];
#pragma unroll
  for (int l = 0; l < 4; l++) {
    int t = tt * 16 + tq * 4 + l;
    out[((size_t)b * 192 + t) * 64 + d] = acc[l] + bb;
  }
}

extern "C" void kernel_launch(void* const* d_in, const int* in_sizes, int n_in,
                              void* d_out, int out_size) {
  const float* inputs = (const float*)d_in[0];
  const float* spec_wr = (const float*)d_in[1];
  const float* spec_wi = (const float*)d_in[2];
  const float* mlp_w = (const float*)d_in[3];
  const float* mlp_b = (const float*)d_in[4];
  float* out = (float*)d_out;

  k_copy<<<256, 256>>>(h_H, h_em, h_tw, h_al);
  k_w2<<<dim3(256, 3), 256>>>(spec_wr, spec_wi);
  k_gemmU<<<dim3(192, 21), 128>>>();
  k_chunksum<<<dim3(24, 21), 256>>>();
  k_coff<<<(21 * 6144 + 255) / 256, 256>>>();
  k_scanG<<<dim3(24, 21), 256>>>();
  k_comb<<<(768 * 192 + 255) / 256, 256>>>(mlp_w);
  k_out<<<dim3(12, 8), 256>>>(inputs, mlp_b, out);
}

// round 6
// speedup vs baseline: 1.2180x; 1.0210x over previous
#include <cuda_runtime.h>
#include <vector>
#include <cmath>

#define HID 256
#define OLEN 192
#define NMODE 32
#define TSUM 1344
#define NCOL 12288   // 192*32*2

// ---------------- host constant tables ----------------
static float h_H[TSUM * HID];
static float h_em[3 * OLEN * HID];
static float h_tw[TSUM * 2];
static float h_al[3 * NMODE * 2];

struct HostInit {
  HostInit() {
    const double PI2 = 6.283185307179586476925286766559;
    for (int si = 0; si < 3; si++) {
      int sc = 1 << si;
      int T = OLEN * sc;
      int uoff = (si == 0) ? 0 : (si == 1) ? 192 : 576;
      double dt = 1.0 / (double)T;
      std::vector<double> M((size_t)HID * HID), R((size_t)HID * (HID + 1)), X((size_t)HID * (HID + 1));
      for (int r = 0; r < HID; r++) {
        for (int c = 0; c < HID; c++) {
          double a = (r < c) ? -1.0 : (((r - c) & 1) ? 1.0 : -1.0);
          a *= (2.0 * r + 1.0);
          M[(size_t)r * HID + c] = (r == c ? 1.0 : 0.0) - 0.5 * dt * a;
          R[(size_t)r * (HID + 1) + c] = (r == c ? 1.0 : 0.0) + 0.5 * dt * a;
        }
        R[(size_t)r * (HID + 1) + HID] = ((r & 1) ? -1.0 : 1.0) * (2.0 * r + 1.0) * dt;
      }
      for (int col = 0; col < HID; col++) {
        int piv = col; double mx = fabs(M[(size_t)col * HID + col]);
        for (int r = col + 1; r < HID; r++) { double v = fabs(M[(size_t)r * HID + col]); if (v > mx) { mx = v; piv = r; } }
        if (piv != col) {
          for (int c = col; c < HID; c++) { double t = M[(size_t)col*HID+c]; M[(size_t)col*HID+c] = M[(size_t)piv*HID+c]; M[(size_t)piv*HID+c] = t; }
          for (int c = 0; c <= HID; c++) { double t = R[(size_t)col*(HID+1)+c]; R[(size_t)col*(HID+1)+c] = R[(size_t)piv*(HID+1)+c]; R[(size_t)piv*(HID+1)+c] = t; }
        }
        double d = M[(size_t)col * HID + col];
        for (int r = col + 1; r < HID; r++) {
          double f = M[(size_t)r * HID + col] / d;
          if (f != 0.0) {
            for (int c = col; c < HID; c++) M[(size_t)r*HID+c] -= f * M[(size_t)col*HID+c];
            for (int c = 0; c <= HID; c++) R[(size_t)r*(HID+1)+c] -= f * R[(size_t)col*(HID+1)+c];
          }
        }
      }
      for (int r = HID - 1; r >= 0; r--) {
        double diag = M[(size_t)r * HID + r];
        for (int c = 0; c <= HID; c++) {
          double s = R[(size_t)r * (HID + 1) + c];
          for (int rr = r + 1; rr < HID; rr++) s -= M[(size_t)r*HID+rr] * X[(size_t)rr*(HID+1)+c];
          X[(size_t)r * (HID + 1) + c] = s / diag;
        }
      }
      std::vector<double> Ad((size_t)HID * HID), h(HID), hn(HID);
      for (int r = 0; r < HID; r++) {
        for (int c = 0; c < HID; c++) Ad[(size_t)r*HID+c] = (double)(float)X[(size_t)r*(HID+1)+c];
        h[r] = (double)(float)X[(size_t)r*(HID+1)+HID];
      }
      for (int u = 0; u < T; u++) {
        for (int i = 0; i < HID; i++) h_H[(size_t)(uoff + u) * HID + i] = (float)h[i];
        for (int i = 0; i < HID; i++) {
          double s = 0; const double* row = &Ad[(size_t)i * HID];
          for (int j = 0; j < HID; j++) s += row[j] * h[j];
          hn[i] = s;
        }
        h.swap(hn);
      }
      for (int t = 0; t < OLEN; t++) {
        int j = T - OLEN + t;
        double x = 1.0 - 2.0 * ((double)j * dt);
        float* dst = &h_em[((size_t)si * OLEN + t) * HID];
        double p0 = 1.0, p1 = x;
        dst[0] = (float)p0; dst[1] = (float)p1;
        for (int n = 1; n < HID - 1; n++) {
          double p2 = ((2.0*n+1.0)*x*p1 - (double)n*p0) / (double)(n+1);
          dst[n+1] = (float)p2; p0 = p1; p1 = p2;
        }
      }
      for (int j = 0; j < T; j++) {
        double th = PI2 * (double)j / (double)T;
        h_tw[(uoff + j) * 2 + 0] = (float)cos(th);
        h_tw[(uoff + j) * 2 + 1] = (float)(-sin(th));
      }
      h_al[(si * NMODE + 0) * 2 + 0] = (float)(1.0 / (double)T);
      h_al[(si * NMODE + 0) * 2 + 1] = 0.0f;
      for (int k = 1; k < NMODE; k++) {
        double th = PI2 * (double)(191 * k) / (double)T;
        h_al[(si * NMODE + k) * 2 + 0] = (float)(2.0 / T * cos(th));
        h_al[(si * NMODE + k) * 2 + 1] = (float)(2.0 / T * sin(th));
      }
    }
  }
};
static HostInit g_init;

// ---------------- device scratch ----------------
__device__ float d_W2[3 * 256 * NCOL];
__device__ float d_U[TSUM * NCOL];
__device__ float d_Cs[21 * 6144 * 2];
__device__ float d_Co[21 * 6144 * 2];
__device__ float d_G[TSUM * 192];
__device__ float d_Gc[768 * 192];
__device__ float d_Hd[TSUM * HID];
__device__ float d_emd[3 * 192 * 256];
__device__ float d_twd[TSUM * 2];
__device__ float d_ald[3 * 32 * 2];
// pre-split, frag-permuted A operands
#define NHP (84 * 8 * 4 * 32)       // u-tiles x chunks x q x lane
#define NEP (3 * 12 * 8 * 4 * 32)   // scale x m-tiles x chunks x q x lane
__device__ float4 d_AhP[NHP];
__device__ float4 d_AlP[NHP];
__device__ float4 d_EhP[NEP];
__device__ float4 d_ElP[NEP];

// ---------------- tf32 helpers ----------------
__device__ __forceinline__ float tf32_rna(float x) {
  unsigned u; asm("cvt.rna.tf32.f32 %0, %1;" : "=r"(u) : "f"(x)); return __uint_as_float(u);
}
__device__ __forceinline__ void mma8(float4& d, unsigned a0, unsigned a1, unsigned a2, unsigned a3,
                                     unsigned b0, unsigned b1) {
  asm("mma.sync.aligned.m16n8k8.row.col.f32.tf32.tf32.f32 "
      "{%0,%1,%2,%3}, {%4,%5,%6,%7}, {%8,%9}, {%0,%1,%2,%3};"
      : "+f"(d.x), "+f"(d.y), "+f"(d.z), "+f"(d.w)
      : "r"(a0), "r"(a1), "r"(a2), "r"(a3), "r"(b0), "r"(b1));
}
__device__ __forceinline__ unsigned f2u(float x) { return __float_as_uint(x); }

// K0: pull host constants via ATS (GB300 C2C)
__global__ void k_copy(const float* __restrict__ hH, const float* __restrict__ hem,
                       const float* __restrict__ htw, const float* __restrict__ hal) {
  int i = blockIdx.x * blockDim.x + threadIdx.x, st = gridDim.x * blockDim.x;
  for (int j = i; j < TSUM * HID; j += st) d_Hd[j] = hH[j];
  for (int j = i; j < 3 * 192 * 256; j += st) d_emd[j] = hem[j];
  for (int j = i; j < TSUM * 2; j += st) d_twd[j] = htw[j];
  for (int j = i; j < 3 * 32 * 2; j += st) d_ald[j] = hal[j];
}

// prep: split+permute H into mma A-fragment order
__global__ void k_prepH() {
  int idx = blockIdx.x * 256 + threadIdx.x;
  if (idx >= NHP) return;
  int lane = idx & 31, q = (idx >> 5) & 3, ch = (idx >> 7) & 7, ut = idx >> 10;
  int r = lane >> 2, cc = lane & 3;
  int row0 = ut * 16 + r;
  int kb = ch * 32 + q * 8 + cc;
  float a0 = d_Hd[(size_t)row0 * 256 + kb];
  float a1 = d_Hd[(size_t)(row0 + 8) * 256 + kb];
  float a2 = d_Hd[(size_t)row0 * 256 + kb + 4];
  float a3 = d_Hd[(size_t)(row0 + 8) * 256 + kb + 4];
  float h0 = tf32_rna(a0), h1 = tf32_rna(a1), h2 = tf32_rna(a2), h3 = tf32_rna(a3);
  d_AhP[idx] = make_float4(h0, h1, h2, h3);
  d_AlP[idx] = make_float4(a0 - h0, a1 - h1, a2 - h2, a3 - h3);
}

// prep: split+permute em into mma A-fragment order
__global__ void k_prepE() {
  int idx = blockIdx.x * 256 + threadIdx.x;
  if (idx >= NEP) return;
  int lane = idx & 31, q = (idx >> 5) & 3, ch = (idx >> 7) & 7;
  int mt = (idx >> 10) % 12, s = (idx >> 10) / 12;
  int r = lane >> 2, cc = lane & 3;
  int row0 = mt * 16 + r;
  int kb = ch * 32 + q * 8 + cc;
  const float* emb = d_emd + (size_t)s * 192 * 256;
  float a0 = emb[(size_t)row0 * 256 + kb];
  float a1 = emb[(size_t)(row0 + 8) * 256 + kb];
  float a2 = emb[(size_t)row0 * 256 + kb + 4];
  float a3 = emb[(size_t)(row0 + 8) * 256 + kb + 4];
  float h0 = tf32_rna(a0), h1 = tf32_rna(a1), h2 = tf32_rna(a2), h3 = tf32_rna(a3);
  d_EhP[idx] = make_float4(h0, h1, h2, h3);
  d_ElP[idx] = make_float4(a0 - h0, a1 - h1, a2 - h2, a3 - h3);
}

// K1 (tensor): W2[s][i][t][2k+reim] = alpha_k * sum_o w[s,i,o,k] * em[s,t,o]
__global__ void k_w2(const float* __restrict__ wr, const float* __restrict__ wi) {
  __shared__ float Bh[32 * 72], Bl[32 * 72];
  int s = blockIdx.y, i = blockIdx.x;
  int tid = threadIdx.x, wid = tid >> 5, lane = tid & 31;
  int wn = (wid & 1) * 32, whalf = wid & 1;
  int r = lane >> 2, cc = lane & 3;
  const float* wrb = wr + (size_t)(s * 256 + i) * 256 * 32;
  const float* wib = wi + (size_t)(s * 256 + i) * 256 * 32;
  float4 acc[3][4];
#pragma unroll
  for (int mt = 0; mt < 3; mt++)
#pragma unroll
    for (int j = 0; j < 4; j++) acc[mt][j] = make_float4(0.f, 0.f, 0.f, 0.f);

  for (int ch = 0; ch < 8; ch++) {
    __syncthreads();
    {
      int row = tid >> 3, qd = tid & 7;
      float4 vr = *(const float4*)(wrb + (size_t)(ch * 32 + row) * 32 + qd * 4);
      float4 vi = *(const float4*)(wib + (size_t)(ch * 32 + row) * 32 + qd * 4);
      float vre[4] = {vr.x, vr.y, vr.z, vr.w};
      float vim[4] = {vi.x, vi.y, vi.z, vi.w};
#pragma unroll
      for (int e = 0; e < 4; e++) {
        int n0 = (qd * 4 + e) * 2;
        int p0 = row * 72 + (n0 & 7) * 8 + (n0 >> 3);
        int n1 = n0 + 1;
        int p1 = row * 72 + (n1 & 7) * 8 + (n1 >> 3);
        float h = tf32_rna(vre[e]); Bh[p0] = h; Bl[p0] = vre[e] - h;
        h = tf32_rna(vim[e]); Bh[p1] = h; Bl[p1] = vim[e] - h;
      }
    }
    __syncthreads();
#pragma unroll
    for (int q = 0; q < 4; q++) {
      float4 b0h = *(const float4*)(Bh + (q * 8 + cc) * 72 + r * 8 + whalf * 4);
      float4 b1h = *(const float4*)(Bh + (q * 8 + cc + 4) * 72 + r * 8 + whalf * 4);
      float4 b0l = *(const float4*)(Bl + (q * 8 + cc) * 72 + r * 8 + whalf * 4);
      float4 b1l = *(const float4*)(Bl + (q * 8 + cc + 4) * 72 + r * 8 + whalf * 4);
      unsigned B0H[4] = {f2u(b0h.x), f2u(b0h.y), f2u(b0h.z), f2u(b0h.w)};
      unsigned B1H[4] = {f2u(b1h.x), f2u(b1h.y), f2u(b1h.z), f2u(b1h.w)};
      unsigned B0L[4] = {f2u(b0l.x), f2u(b0l.y), f2u(b0l.z), f2u(b0l.w)};
      unsigned B1L[4] = {f2u(b1l.x), f2u(b1l.y), f2u(b1l.z), f2u(b1l.w)};
#pragma unroll
      for (int mt = 0; mt < 3; mt++) {
        int mtile = (wid >> 1) * 3 + mt;
        int eidx = (((s * 12 + mtile) * 8 + ch) * 4 + q) * 32 + lane;
        float4 ah = d_EhP[eidx];
        float4 al = d_ElP[eidx];
        unsigned h0 = f2u(ah.x), h1 = f2u(ah.y), h2 = f2u(ah.z), h3 = f2u(ah.w);
        unsigned l0 = f2u(al.x), l1 = f2u(al.y), l2 = f2u(al.z), l3 = f2u(al.w);
#pragma unroll
        for (int j = 0; j < 4; j++) {
          mma8(acc[mt][j], h0, h1, h2, h3, B0H[j], B1H[j]);
          mma8(acc[mt][j], h0, h1, h2, h3, B0L[j], B1L[j]);
          mma8(acc[mt][j], l0, l1, l2, l3, B0H[j], B1H[j]);
        }
      }
    }
  }
  float* outb = d_W2 + (size_t)(s * 256 + i) * NCOL;
#pragma unroll
  for (int mt = 0; mt < 3; mt++) {
#pragma unroll
    for (int j = 0; j < 4; j++) {
      int ncol = wn + j * 8 + 2 * cc;
      int kmode = ncol >> 1;
      float alr = d_ald[(s * 32 + kmode) * 2], ali = d_ald[(s * 32 + kmode) * 2 + 1];
      float4 c = acc[mt][j];
      int t0 = (wid >> 1) * 48 + mt * 16 + r;
      float2 lo = make_float2(alr * c.x - ali * c.y, alr * c.y + ali * c.x);
      float2 hi = make_float2(alr * c.z - ali * c.w, alr * c.w + ali * c.z);
      *(float2*)(outb + (size_t)t0 * 64 + ncol) = lo;
      *(float2*)(outb + (size_t)(t0 + 8) * 64 + ncol) = hi;
    }
  }
}

// K2 (tensor): U[u, n] = sum_i H[u,i] * W2[s(u)][i, n]
// Block: 192 u x 64 n, 12 warps (16 u each), K chunks of 32.
__global__ void k_gemmU() {
  __shared__ float Bh[32 * 72], Bl[32 * 72];
  int bn = blockIdx.x, ub = blockIdx.y;
  int u0 = ub * 192;
  int s = (u0 < 192) ? 0 : (u0 < 576) ? 1 : 2;
  const float* B = d_W2 + (size_t)s * 256 * NCOL + bn * 64;
  float* C = d_U + (size_t)u0 * NCOL + bn * 64;
  int tid = threadIdx.x, wid = tid >> 5, lane = tid & 31;
  int r = lane >> 2, cc = lane & 3;
  int ut = ub * 12 + wid;
  float4 acc[8];
#pragma unroll
  for (int j = 0; j < 8; j++) acc[j] = make_float4(0.f, 0.f, 0.f, 0.f);

  for (int ch = 0; ch < 8; ch++) {
    __syncthreads();
    for (int it = tid; it < 512; it += 384) {
      int row = it >> 4, qd = it & 15;
      float4 v = *(const float4*)(B + (size_t)(ch * 32 + row) * NCOL + qd * 4);
      float vv[4] = {v.x, v.y, v.z, v.w};
#pragma unroll
      for (int e = 0; e < 4; e++) {
        int n = qd * 4 + e;
        int p = row * 72 + (n & 7) * 8 + (n >> 3);
        float h = tf32_rna(vv[e]);
        Bh[p] = h; Bl[p] = vv[e] - h;
      }
    }
    __syncthreads();
#pragma unroll
    for (int q = 0; q < 4; q++) {
      int aidx = ((ut * 8 + ch) * 4 + q) * 32 + lane;
      float4 ah = d_AhP[aidx];
      float4 al = d_AlP[aidx];
      unsigned h0 = f2u(ah.x), h1 = f2u(ah.y), h2 = f2u(ah.z), h3 = f2u(ah.w);
      unsigned l0 = f2u(al.x), l1 = f2u(al.y), l2 = f2u(al.z), l3 = f2u(al.w);
      float4 v0h = *(const float4*)(Bh + (q * 8 + cc) * 72 + r * 8);
      float4 v0h2 = *(const float4*)(Bh + (q * 8 + cc) * 72 + r * 8 + 4);
      float4 v1h = *(const float4*)(Bh + (q * 8 + cc + 4) * 72 + r * 8);
      float4 v1h2 = *(const float4*)(Bh + (q * 8 + cc + 4) * 72 + r * 8 + 4);
      float4 v0l = *(const float4*)(Bl + (q * 8 + cc) * 72 + r * 8);
      float4 v0l2 = *(const float4*)(Bl + (q * 8 + cc) * 72 + r * 8 + 4);
      float4 v1l = *(const float4*)(Bl + (q * 8 + cc + 4) * 72 + r * 8);
      float4 v1l2 = *(const float4*)(Bl + (q * 8 + cc + 4) * 72 + r * 8 + 4);
      unsigned B0H[8] = {f2u(v0h.x), f2u(v0h.y), f2u(v0h.z), f2u(v0h.w),
                         f2u(v0h2.x), f2u(v0h2.y), f2u(v0h2.z), f2u(v0h2.w)};
      unsigned B1H[8] = {f2u(v1h.x), f2u(v1h.y), f2u(v1h.z), f2u(v1h.w),
                         f2u(v1h2.x), f2u(v1h2.y), f2u(v1h2.z), f2u(v1h2.w)};
      unsigned B0L[8] = {f2u(v0l.x), f2u(v0l.y), f2u(v0l.z), f2u(v0l.w),
                         f2u(v0l2.x), f2u(v0l2.y), f2u(v0l2.z), f2u(v0l2.w)};
      unsigned B1L[8] = {f2u(v1l.x), f2u(v1l.y), f2u(v1l.z), f2u(v1l.w),
                         f2u(v1l2.x), f2u(v1l2.y), f2u(v1l2.z), f2u(v1l2.w)};
#pragma unroll
      for (int j = 0; j < 8; j++) {
        mma8(acc[j], h0, h1, h2, h3, B0H[j], B1H[j]);
        mma8(acc[j], h0, h1, h2, h3, B0L[j], B1L[j]);
        mma8(acc[j], l0, l1, l2, l3, B0H[j], B1H[j]);
      }
    }
  }
#pragma unroll
  for (int j = 0; j < 8; j++) {
    float* cp = C + (size_t)(wid * 16 + r) * NCOL + j * 8 + 2 * cc;
    *(float2*)cp = make_float2(acc[j].x, acc[j].y);
    *(float2*)(cp + (size_t)8 * NCOL) = make_float2(acc[j].z, acc[j].w);
  }
}

// K3a: per-chunk (64 u) twiddled sums
__global__ void k_chunksum() {
  int tk = blockIdx.x * 256 + threadIdx.x;
  int cg = blockIdx.y;
  int s, coff;
  if (cg < 3) { s = 0; coff = 0; } else if (cg < 9) { s = 1; coff = 3; } else { s = 2; coff = 9; }
  int T = 192 << s;
  int uoff = (s == 0) ? 0 : (s == 1) ? 192 : 576;
  int u0 = (cg - coff) * 64, k = tk & 31;
  int j = (u0 * k) % T;
  const float2* tw = (const float2*)d_twd + uoff;
  const float2* Up = (const float2*)d_U + (size_t)(uoff + u0) * 6144 + tk;
  float2 run = make_float2(0.f, 0.f);
  for (int u = 0; u < 64; u++) {
    float2 x = Up[(size_t)u * 6144];
    float2 w = tw[j];
    run.x += w.x * x.x - w.y * x.y;
    run.y += w.x * x.y + w.y * x.x;
    j += k; if (j >= T) j -= T;
  }
  ((float2*)d_Cs)[cg * 6144 + tk] = run;
}

// K3b: exclusive scan of chunk sums within each scale
__global__ void k_coff() {
  int idx = blockIdx.x * 256 + threadIdx.x;
  if (idx >= 21 * 6144) return;
  int cg = idx / 6144, tk = idx % 6144;
  int c0 = (cg < 3) ? 0 : (cg < 9) ? 3 : 9;
  float2 sum = make_float2(0.f, 0.f);
  for (int c = c0; c < cg; c++) { float2 v = ((float2*)d_Cs)[c * 6144 + tk]; sum.x += v.x; sum.y += v.y; }
  ((float2*)d_Co)[cg * 6144 + tk] = sum;
}

// K3c: recompute running prefix (seeded) and reduce into G
__global__ void k_scanG() {
  int tk = blockIdx.x * 256 + threadIdx.x;
  int cg = blockIdx.y;
  int s, coff;
  if (cg < 3) { s = 0; coff = 0; } else if (cg < 9) { s = 1; coff = 3; } else { s = 2; coff = 9; }
  int T = 192 << s;
  int uoff = (s == 0) ? 0 : (s == 1) ? 192 : 576;
  int u0 = (cg - coff) * 64;
  int k = tk & 31, t = tk >> 5, lane = threadIdx.x & 31;
  int j = (u0 * k) % T;
  int tau0 = T - 1 - u0;
  int j2 = (tau0 * k) % T;
  const float2* tw = (const float2*)d_twd + uoff;
  const float2* Up = (const float2*)d_U + (size_t)(uoff + u0) * 6144 + tk;
  float2 run = ((const float2*)d_Co)[cg * 6144 + tk];
  for (int u = 0; u < 64; u++) {
    float2 x = Up[(size_t)u * 6144];
    float2 w = tw[j];
    run.x += w.x * x.x - w.y * x.y;
    run.y += w.x * x.y + w.y * x.x;
    float2 w2 = tw[j2];
    float p = w2.x * run.x - w2.y * run.y;
#pragma unroll
    for (int off = 16; off; off >>= 1) p += __shfl_xor_sync(0xffffffffu, p, off);
    if (!lane) d_G[(size_t)(uoff + tau0 - u) * 192 + t] = p;
    j += k; if (j >= T) j -= T;
    j2 -= k; if (j2 < 0) j2 += T;
  }
}

// K5: combine scales with mlp weights
__global__ void k_comb(const float* __restrict__ mw) {
  int idx = blockIdx.x * 256 + threadIdx.x;
  if (idx >= 768 * 192) return;
  int jj = idx / 192, t = idx % 192;
  float acc = mw[2] * d_G[(size_t)(576 + jj) * 192 + t];
  if (jj >= 384) acc += mw[1] * d_G[(size_t)(192 + jj - 384) * 192 + t];
  if (jj >= 576) acc += mw[0] * d_G[(size_t)(jj - 576) * 192 + t];
  d_Gc[idx] = acc;
}

// K6: out[b,t,d] = mlp_b + sum_j inputs[b,j,d] * Gc[j,t]
__global__ void k_out(const float* __restrict__ inp, const float* __restrict__ mb, float* __restrict__ out) {
  __shared__ float fs[4096];
  int b = blockIdx.y, tt = blockIdx.x;
  int tid = threadIdx.x, d = tid & 63, tq = tid >> 6;
  float acc[4] = {0.f, 0.f, 0.f, 0.f};
  const float* ib = inp + (size_t)b * 768 * 64;
  for (int j0 = 0; j0 < 768; j0 += 64) {
    __syncthreads();
    for (int e = tid; e < 4096; e += 256) fs[e] = ib[(size_t)j0 * 64 + e];
    __syncthreads();
    for (int jj = 0; jj < 64; jj++) {
      float f = fs[jj * 64 + d];
#pragma unroll
      for (int l = 0; l < 4; l++) {
        int t = tt * 16 + tq * 4 + l;
        acc[l] += f * d_Gc[(size_t)(j0 + jj) * 192 + t];
      }
    }
  }
  float bb = mb[0];
#pragma unroll
  for (int l = 0; l < 4; l++) {
    int t = tt * 16 + tq * 4 + l;
    out[((size_t)b * 192 + t) * 64 + d] = acc[l] + bb;
  }
}

extern "C" void kernel_launch(void* const* d_in, const int* in_sizes, int n_in,
                              void* d_out, int out_size) {
  const float* inputs = (const float*)d_in[0];
  const float* spec_wr = (const float*)d_in[1];
  const float* spec_wi = (const float*)d_in[2];
  const float* mlp_w = (const float*)d_in[3];
  const float* mlp_b = (const float*)d_in[4];
  float* out = (float*)d_out;

  k_copy<<<256, 256>>>(h_H, h_em, h_tw, h_al);
  k_prepH<<<(NHP + 255) / 256, 256>>>();
  k_prepE<<<(NEP + 255) / 256, 256>>>();
  k_w2<<<dim3(256, 3), 256>>>(spec_wr, spec_wi);
  k_gemmU<<<dim3(192, 7), 384>>>();
  k_chunksum<<<dim3(24, 21), 256>>>();
  k_coff<<<(21 * 6144 + 255) / 256, 256>>>();
  k_scanG<<<dim3(24, 21), 256>>>();
  k_comb<<<(768 * 192 + 255) / 256, 256>>>(mlp_w);
  k_out<<<dim3(12, 8), 256>>>(inputs, mlp_b, out);
}

// round 7
// speedup vs baseline: 1.6569x; 1.3603x over previous
#include <cuda_runtime.h>
#include <cuda_bf16.h>
#include <vector>
#include <cmath>
#include <cstring>

#define HID 256
#define OLEN 192
#define NMODE 32
#define TSUM 1344
#define NCOL 12288   // 192*32*2
#define NH4 (84 * 16 * 32)      // H-frag uint4 count
#define NE4 (3 * 12 * 16 * 32)  // em-frag uint4 count

// ---------------- host constant tables ----------------
static float h_H[TSUM * HID];
static float h_em[3 * OLEN * HID];
static float h_tw[TSUM * 2];
static float h_al[3 * NMODE * 2];
static unsigned h_HfH[NH4 * 4], h_HfL[NH4 * 4];
static unsigned h_EfH[NE4 * 4], h_EfL[NE4 * 4];

static inline unsigned short f2bf(float x) {
  unsigned u; memcpy(&u, &x, 4);
  return (unsigned short)((u + 0x7FFF + ((u >> 16) & 1)) >> 16);
}
static inline float bff(unsigned short b) {
  unsigned u = (unsigned)b << 16; float f; memcpy(&f, &u, 4); return f;
}
static inline void pack_pair(float e0, float e1, unsigned& hi, unsigned& lo) {
  unsigned short h0 = f2bf(e0), h1 = f2bf(e1);
  unsigned short l0 = f2bf(e0 - bff(h0)), l1 = f2bf(e1 - bff(h1));
  hi = ((unsigned)h1 << 16) | h0;
  lo = ((unsigned)l1 << 16) | l0;
}

struct HostInit {
  HostInit() {
    const double PI2 = 6.283185307179586476925286766559;
    for (int si = 0; si < 3; si++) {
      int sc = 1 << si;
      int T = OLEN * sc;
      int uoff = (si == 0) ? 0 : (si == 1) ? 192 : 576;
      double dt = 1.0 / (double)T;
      std::vector<double> M((size_t)HID * HID), R((size_t)HID * (HID + 1)), X((size_t)HID * (HID + 1));
      for (int r = 0; r < HID; r++) {
        for (int c = 0; c < HID; c++) {
          double a = (r < c) ? -1.0 : (((r - c) & 1) ? 1.0 : -1.0);
          a *= (2.0 * r + 1.0);
          M[(size_t)r * HID + c] = (r == c ? 1.0 : 0.0) - 0.5 * dt * a;
          R[(size_t)r * (HID + 1) + c] = (r == c ? 1.0 : 0.0) + 0.5 * dt * a;
        }
        R[(size_t)r * (HID + 1) + HID] = ((r & 1) ? -1.0 : 1.0) * (2.0 * r + 1.0) * dt;
      }
      for (int col = 0; col < HID; col++) {
        int piv = col; double mx = fabs(M[(size_t)col * HID + col]);
        for (int r = col + 1; r < HID; r++) { double v = fabs(M[(size_t)r * HID + col]); if (v > mx) { mx = v; piv = r; } }
        if (piv != col) {
          for (int c = col; c < HID; c++) { double t = M[(size_t)col*HID+c]; M[(size_t)col*HID+c] = M[(size_t)piv*HID+c]; M[(size_t)piv*HID+c] = t; }
          for (int c = 0; c <= HID; c++) { double t = R[(size_t)col*(HID+1)+c]; R[(size_t)col*(HID+1)+c] = R[(size_t)piv*(HID+1)+c]; R[(size_t)piv*(HID+1)+c] = t; }
        }
        double d = M[(size_t)col * HID + col];
        for (int r = col + 1; r < HID; r++) {
          double f = M[(size_t)r * HID + col] / d;
          if (f != 0.0) {
            for (int c = col; c < HID; c++) M[(size_t)r*HID+c] -= f * M[(size_t)col*HID+c];
            for (int c = 0; c <= HID; c++) R[(size_t)r*(HID+1)+c] -= f * R[(size_t)col*(HID+1)+c];
          }
        }
      }
      for (int r = HID - 1; r >= 0; r--) {
        double diag = M[(size_t)r * HID + r];
        for (int c = 0; c <= HID; c++) {
          double s = R[(size_t)r * (HID + 1) + c];
          for (int rr = r + 1; rr < HID; rr++) s -= M[(size_t)r*HID+rr] * X[(size_t)rr*(HID+1)+c];
          X[(size_t)r * (HID + 1) + c] = s / diag;
        }
      }
      std::vector<double> Ad((size_t)HID * HID), h(HID), hn(HID);
      for (int r = 0; r < HID; r++) {
        for (int c = 0; c < HID; c++) Ad[(size_t)r*HID+c] = (double)(float)X[(size_t)r*(HID+1)+c];
        h[r] = (double)(float)X[(size_t)r*(HID+1)+HID];
      }
      for (int u = 0; u < T; u++) {
        for (int i = 0; i < HID; i++) h_H[(size_t)(uoff + u) * HID + i] = (float)h[i];
        for (int i = 0; i < HID; i++) {
          double s = 0; const double* row = &Ad[(size_t)i * HID];
          for (int j = 0; j < HID; j++) s += row[j] * h[j];
          hn[i] = s;
        }
        h.swap(hn);
      }
      for (int t = 0; t < OLEN; t++) {
        int j = T - OLEN + t;
        double x = 1.0 - 2.0 * ((double)j * dt);
        float* dst = &h_em[((size_t)si * OLEN + t) * HID];
        double p0 = 1.0, p1 = x;
        dst[0] = (float)p0; dst[1] = (float)p1;
        for (int n = 1; n < HID - 1; n++) {
          double p2 = ((2.0*n+1.0)*x*p1 - (double)n*p0) / (double)(n+1);
          dst[n+1] = (float)p2; p0 = p1; p1 = p2;
        }
      }
      for (int j = 0; j < T; j++) {
        double th = PI2 * (double)j / (double)T;
        h_tw[(uoff + j) * 2 + 0] = (float)cos(th);
        h_tw[(uoff + j) * 2 + 1] = (float)(-sin(th));
      }
      h_al[(si * NMODE + 0) * 2 + 0] = (float)(1.0 / (double)T);
      h_al[(si * NMODE + 0) * 2 + 1] = 0.0f;
      for (int k = 1; k < NMODE; k++) {
        double th = PI2 * (double)(191 * k) / (double)T;
        h_al[(si * NMODE + k) * 2 + 0] = (float)(2.0 / T * cos(th));
        h_al[(si * NMODE + k) * 2 + 1] = (float)(2.0 / T * sin(th));
      }
    }
    // H fragments in m16n8k16 A order (hi/lo bf16 pairs)
    for (int ut = 0; ut < 84; ut++)
      for (int mmg = 0; mmg < 16; mmg++)
        for (int lane = 0; lane < 32; lane++) {
          int r = lane >> 2, c = lane & 3;
          int r0 = ut * 16 + r, r1 = r0 + 8, i0 = mmg * 16;
          int idx = (((ut * 16) + mmg) * 32 + lane) * 4;
          pack_pair(h_H[(size_t)r0*256 + i0+2*c],   h_H[(size_t)r0*256 + i0+2*c+1], h_HfH[idx+0], h_HfL[idx+0]);
          pack_pair(h_H[(size_t)r1*256 + i0+2*c],   h_H[(size_t)r1*256 + i0+2*c+1], h_HfH[idx+1], h_HfL[idx+1]);
          pack_pair(h_H[(size_t)r0*256 + i0+2*c+8], h_H[(size_t)r0*256 + i0+2*c+9], h_HfH[idx+2], h_HfL[idx+2]);
          pack_pair(h_H[(size_t)r1*256 + i0+2*c+8], h_H[(size_t)r1*256 + i0+2*c+9], h_HfH[idx+3], h_HfL[idx+3]);
        }
    // em fragments
    for (int s = 0; s < 3; s++)
      for (int mt = 0; mt < 12; mt++)
        for (int mmg = 0; mmg < 16; mmg++)
          for (int lane = 0; lane < 32; lane++) {
            int r = lane >> 2, c = lane & 3;
            int r0 = mt * 16 + r, r1 = r0 + 8, o0 = mmg * 16;
            const float* A = h_em + (size_t)s * 192 * 256;
            int idx = ((((s * 12 + mt) * 16) + mmg) * 32 + lane) * 4;
            pack_pair(A[(size_t)r0*256 + o0+2*c],   A[(size_t)r0*256 + o0+2*c+1], h_EfH[idx+0], h_EfL[idx+0]);
            pack_pair(A[(size_t)r1*256 + o0+2*c],   A[(size_t)r1*256 + o0+2*c+1], h_EfH[idx+1], h_EfL[idx+1]);
            pack_pair(A[(size_t)r0*256 + o0+2*c+8], A[(size_t)r0*256 + o0+2*c+9], h_EfH[idx+2], h_EfL[idx+2]);
            pack_pair(A[(size_t)r1*256 + o0+2*c+8], A[(size_t)r1*256 + o0+2*c+9], h_EfH[idx+3], h_EfL[idx+3]);
          }
  }
};
static HostInit g_init;

// ---------------- device scratch ----------------
__device__ uint4 d_HfH[NH4], d_HfL[NH4];
__device__ uint4 d_EfH[NE4], d_EfL[NE4];
__device__ __nv_bfloat16 d_W2h[3 * 256 * NCOL];
__device__ __nv_bfloat16 d_W2l[3 * 256 * NCOL];
__device__ float d_U[TSUM * NCOL];
__device__ float d_Cs[21 * 6144 * 2];
__device__ float d_Co[21 * 6144 * 2];
__device__ float d_G[TSUM * 192];
__device__ float d_Gc[768 * 192];
__device__ float d_twd[TSUM * 2];
__device__ float d_ald[3 * 32 * 2];

__device__ __forceinline__ void mma16(float4& d, const uint4& a, unsigned b0, unsigned b1) {
  asm("mma.sync.aligned.m16n8k16.row.col.f32.bf16.bf16.f32 "
      "{%0,%1,%2,%3},{%4,%5,%6,%7},{%8,%9},{%0,%1,%2,%3};"
      : "+f"(d.x), "+f"(d.y), "+f"(d.z), "+f"(d.w)
      : "r"(a.x), "r"(a.y), "r"(a.z), "r"(a.w), "r"(b0), "r"(b1));
}

__device__ __forceinline__ unsigned pkbf(float a, float b) {
  __nv_bfloat16 ha = __float2bfloat16_rn(a), hb = __float2bfloat16_rn(b);
  return ((unsigned)__bfloat16_as_ushort(hb) << 16) | __bfloat16_as_ushort(ha);
}

// K0: pull host constants via ATS (GB300 C2C)
__global__ void k_copy(const float* __restrict__ htw, const float* __restrict__ hal,
                       const uint4* __restrict__ hHfH, const uint4* __restrict__ hHfL,
                       const uint4* __restrict__ hEfH, const uint4* __restrict__ hEfL) {
  int i = blockIdx.x * blockDim.x + threadIdx.x, st = gridDim.x * blockDim.x;
  for (int j = i; j < TSUM * 2; j += st) d_twd[j] = htw[j];
  for (int j = i; j < 3 * 32 * 2; j += st) d_ald[j] = hal[j];
  for (int j = i; j < NH4; j += st) { d_HfH[j] = hHfH[j]; d_HfL[j] = hHfL[j]; }
  for (int j = i; j < NE4; j += st) { d_EfH[j] = hEfH[j]; d_EfL[j] = hEfL[j]; }
}

// K1: W2[s][i][t][2k+reim] = alpha_k * sum_o w[s,i,o,k] * em[s,t,o]
// bf16 m16n8k16, 3-pass split. Block = (i, s): C[192 x 64], K = 256 (o).
__global__ void k_w2(const float* __restrict__ wr, const float* __restrict__ wi) {
  __shared__ unsigned Bph[16 * 72], Bpl[16 * 72];
  int s = blockIdx.y, i = blockIdx.x;
  int tid = threadIdx.x, wid = tid >> 5, lane = tid & 31;
  int whalf = wid & 1, wg = wid >> 1;
  int r = lane >> 2, c = lane & 3;
  const float* wrb = wr + (size_t)(s * 256 + i) * 8192;
  const float* wib = wi + (size_t)(s * 256 + i) * 8192;
  float4 acc[3][4];
#pragma unroll
  for (int mt = 0; mt < 3; mt++)
#pragma unroll
    for (int j = 0; j < 4; j++) acc[mt][j] = make_float4(0.f, 0.f, 0.f, 0.f);
  int o2s = tid >> 4, kp = tid & 15;

  for (int ch = 0; ch < 8; ch++) {
    __syncthreads();
    {  // stage 32 o rows as paired bf16 hi/lo
      int oa = ch * 32 + 2 * o2s;
      float2 ra = *(const float2*)(wrb + (size_t)oa * 32 + 2 * kp);
      float2 rb = *(const float2*)(wrb + (size_t)(oa + 1) * 32 + 2 * kp);
      float2 ia = *(const float2*)(wib + (size_t)oa * 32 + 2 * kp);
      float2 ib = *(const float2*)(wib + (size_t)(oa + 1) * 32 + 2 * kp);
      float va[4] = {ra.x, ia.x, ra.y, ia.y};
      float vb[4] = {rb.x, ib.x, rb.y, ib.y};
#pragma unroll
      for (int e = 0; e < 4; e++) {
        int n = 4 * kp + e;
        int p = o2s * 72 + (n & 7) * 8 + (n >> 3);
        __nv_bfloat16 ha = __float2bfloat16_rn(va[e]), hb = __float2bfloat16_rn(vb[e]);
        Bph[p] = ((unsigned)__bfloat16_as_ushort(hb) << 16) | __bfloat16_as_ushort(ha);
        Bpl[p] = pkbf(va[e] - __bfloat162float(ha), vb[e] - __bfloat162float(hb));
      }
    }
    __syncthreads();
#pragma unroll
    for (int m = 0; m < 2; m++) {
      uint4 b0h = *(const uint4*)&Bph[(8 * m + c) * 72 + r * 8 + whalf * 4];
      uint4 b1h = *(const uint4*)&Bph[(8 * m + c + 4) * 72 + r * 8 + whalf * 4];
      uint4 b0l = *(const uint4*)&Bpl[(8 * m + c) * 72 + r * 8 + whalf * 4];
      uint4 b1l = *(const uint4*)&Bpl[(8 * m + c + 4) * 72 + r * 8 + whalf * 4];
      const unsigned* p0h = (const unsigned*)&b0h;
      const unsigned* p1h = (const unsigned*)&b1h;
      const unsigned* p0l = (const unsigned*)&b0l;
      const unsigned* p1l = (const unsigned*)&b1l;
      int mmg = ch * 2 + m;
#pragma unroll
      for (int mt = 0; mt < 3; mt++) {
        int mtile = wg * 3 + mt;
        uint4 ah = d_EfH[((s * 12 + mtile) * 16 + mmg) * 32 + lane];
        uint4 al = d_EfL[((s * 12 + mtile) * 16 + mmg) * 32 + lane];
#pragma unroll
        for (int j = 0; j < 4; j++) {
          mma16(acc[mt][j], ah, p0h[j], p1h[j]);
          mma16(acc[mt][j], ah, p0l[j], p1l[j]);
          mma16(acc[mt][j], al, p0h[j], p1h[j]);
        }
      }
    }
  }
  // epilogue: alpha-scale (complex), store bf16 hi/lo planes
  size_t base0 = (size_t)(s * 256 + i) * NCOL;
#pragma unroll
  for (int mt = 0; mt < 3; mt++) {
#pragma unroll
    for (int j = 0; j < 4; j++) {
      int ncol = whalf * 32 + j * 8 + 2 * c;
      int kmode = ncol >> 1;
      float alr = d_ald[(s * 32 + kmode) * 2], ali = d_ald[(s * 32 + kmode) * 2 + 1];
      float4 cv = acc[mt][j];
      int t0 = wg * 48 + mt * 16 + r;
      float re0 = alr * cv.x - ali * cv.y, im0 = alr * cv.y + ali * cv.x;
      float re1 = alr * cv.z - ali * cv.w, im1 = alr * cv.w + ali * cv.z;
      size_t e0 = base0 + (size_t)t0 * 64 + ncol;
      size_t e1 = base0 + (size_t)(t0 + 8) * 64 + ncol;
      __nv_bfloat16 h0r = __float2bfloat16_rn(re0), h0i = __float2bfloat16_rn(im0);
      __nv_bfloat16 h1r = __float2bfloat16_rn(re1), h1i = __float2bfloat16_rn(im1);
      *(unsigned*)(d_W2h + e0) = ((unsigned)__bfloat16_as_ushort(h0i) << 16) | __bfloat16_as_ushort(h0r);
      *(unsigned*)(d_W2h + e1) = ((unsigned)__bfloat16_as_ushort(h1i) << 16) | __bfloat16_as_ushort(h1r);
      *(unsigned*)(d_W2l + e0) = pkbf(re0 - __bfloat162float(h0r), im0 - __bfloat162float(h0i));
      *(unsigned*)(d_W2l + e1) = pkbf(re1 - __bfloat162float(h1r), im1 - __bfloat162float(h1i));
    }
  }
}

// K2: U[u, n] = sum_i H[u,i] * W2[s(u)][i, n]  bf16 m16n8k16, 3-pass split.
// Block: 192 u x 64 n, 12 warps (16 u each), K = 256 (i) in chunks of 32.
__global__ void k_gemmU() {
  __shared__ unsigned Bph[16 * 72], Bpl[16 * 72];
  int bn = blockIdx.x, ub = blockIdx.y;
  int s = (ub == 0) ? 0 : (ub < 3) ? 1 : 2;
  float* C = d_U + (size_t)ub * 192 * NCOL + bn * 64;
  int tid = threadIdx.x, wid = tid >> 5, lane = tid & 31;
  int r = lane >> 2, c = lane & 3;
  int ut = ub * 12 + wid;
  float4 acc[8];
#pragma unroll
  for (int j = 0; j < 8; j++) acc[j] = make_float4(0.f, 0.f, 0.f, 0.f);

  for (int ch = 0; ch < 8; ch++) {
    __syncthreads();
    if (tid < 256) {  // stage: pair consecutive-i rows of W2h/W2l
      int pairsel = tid >> 7, t2 = tid & 127;
      int k2 = t2 >> 3, oc = t2 & 7;
      const __nv_bfloat16* base = pairsel ? d_W2l : d_W2h;
      const __nv_bfloat16* src = base + (size_t)(s * 256 + ch * 32 + 2 * k2) * NCOL + bn * 64 + oc * 8;
      uint4 va = *(const uint4*)src;
      uint4 vb = *(const uint4*)(src + NCOL);
      unsigned* dst = pairsel ? Bpl : Bph;
      const unsigned* pa = (const unsigned*)&va;
      const unsigned* pb = (const unsigned*)&vb;
#pragma unroll
      for (int h2 = 0; h2 < 4; h2++) {
        int n0 = oc * 8 + h2 * 2, n1 = n0 + 1;
        dst[k2 * 72 + (n0 & 7) * 8 + (n0 >> 3)] = __byte_perm(pa[h2], pb[h2], 0x5410);
        dst[k2 * 72 + (n1 & 7) * 8 + (n1 >> 3)] = __byte_perm(pa[h2], pb[h2], 0x7632);
      }
    }
    __syncthreads();
#pragma unroll
    for (int m = 0; m < 2; m++) {
      int mmg = ch * 2 + m;
      uint4 ah = d_HfH[(ut * 16 + mmg) * 32 + lane];
      uint4 al = d_HfL[(ut * 16 + mmg) * 32 + lane];
#pragma unroll
      for (int half = 0; half < 2; half++) {
        uint4 b0h = *(const uint4*)&Bph[(8 * m + c) * 72 + r * 8 + half * 4];
        uint4 b1h = *(const uint4*)&Bph[(8 * m + c + 4) * 72 + r * 8 + half * 4];
        uint4 b0l = *(const uint4*)&Bpl[(8 * m + c) * 72 + r * 8 + half * 4];
        uint4 b1l = *(const uint4*)&Bpl[(8 * m + c + 4) * 72 + r * 8 + half * 4];
        const unsigned* p0h = (const unsigned*)&b0h;
        const unsigned* p1h = (const unsigned*)&b1h;
        const unsigned* p0l = (const unsigned*)&b0l;
        const unsigned* p1l = (const unsigned*)&b1l;
#pragma unroll
        for (int j = 0; j < 4; j++) {
          int jj = half * 4 + j;
          mma16(acc[jj], ah, p0h[j], p1h[j]);
          mma16(acc[jj], ah, p0l[j], p1l[j]);
          mma16(acc[jj], al, p0h[j], p1h[j]);
        }
      }
    }
  }
#pragma unroll
  for (int j = 0; j < 8; j++) {
    float* cp = C + (size_t)(wid * 16 + r) * NCOL + j * 8 + 2 * c;
    *(float2*)cp = make_float2(acc[j].x, acc[j].y);
    *(float2*)(cp + (size_t)8 * NCOL) = make_float2(acc[j].z, acc[j].w);
  }
}

// K3a: per-chunk (64 u) twiddled sums
__global__ void k_chunksum() {
  int tk = blockIdx.x * 256 + threadIdx.x;
  int cg = blockIdx.y;
  int s, coff;
  if (cg < 3) { s = 0; coff = 0; } else if (cg < 9) { s = 1; coff = 3; } else { s = 2; coff = 9; }
  int T = 192 << s;
  int uoff = (s == 0) ? 0 : (s == 1) ? 192 : 576;
  int u0 = (cg - coff) * 64, k = tk & 31;
  int j = (u0 * k) % T;
  const float2* tw = (const float2*)d_twd + uoff;
  const float2* Up = (const float2*)d_U + (size_t)(uoff + u0) * 6144 + tk;
  float2 run = make_float2(0.f, 0.f);
  for (int u = 0; u < 64; u++) {
    float2 x = Up[(size_t)u * 6144];
    float2 w = tw[j];
    run.x += w.x * x.x - w.y * x.y;
    run.y += w.x * x.y + w.y * x.x;
    j += k; if (j >= T) j -= T;
  }
  ((float2*)d_Cs)[cg * 6144 + tk] = run;
}

// K3b: exclusive scan of chunk sums within each scale
__global__ void k_coff() {
  int idx = blockIdx.x * 256 + threadIdx.x;
  if (idx >= 21 * 6144) return;
  int cg = idx / 6144, tk = idx % 6144;
  int c0 = (cg < 3) ? 0 : (cg < 9) ? 3 : 9;
  float2 sum = make_float2(0.f, 0.f);
  for (int c = c0; c < cg; c++) { float2 v = ((float2*)d_Cs)[c * 6144 + tk]; sum.x += v.x; sum.y += v.y; }
  ((float2*)d_Co)[cg * 6144 + tk] = sum;
}

// K3c: recompute running prefix (seeded) and reduce into G
__global__ void k_scanG() {
  int tk = blockIdx.x * 256 + threadIdx.x;
  int cg = blockIdx.y;
  int s, coff;
  if (cg < 3) { s = 0; coff = 0; } else if (cg < 9) { s = 1; coff = 3; } else { s = 2; coff = 9; }
  int T = 192 << s;
  int uoff = (s == 0) ? 0 : (s == 1) ? 192 : 576;
  int u0 = (cg - coff) * 64;
  int k = tk & 31, t = tk >> 5, lane = threadIdx.x & 31;
  int j = (u0 * k) % T;
  int tau0 = T - 1 - u0;
  int j2 = (tau0 * k) % T;
  const float2* tw = (const float2*)d_twd + uoff;
  const float2* Up = (const float2*)d_U + (size_t)(uoff + u0) * 6144 + tk;
  float2 run = ((const float2*)d_Co)[cg * 6144 + tk];
  for (int u = 0; u < 64; u++) {
    float2 x = Up[(size_t)u * 6144];
    float2 w = tw[j];
    run.x += w.x * x.x - w.y * x.y;
    run.y += w.x * x.y + w.y * x.x;
    float2 w2 = tw[j2];
    float p = w2.x * run.x - w2.y * run.y;
#pragma unroll
    for (int off = 16; off; off >>= 1) p += __shfl_xor_sync(0xffffffffu, p, off);
    if (!lane) d_G[(size_t)(uoff + tau0 - u) * 192 + t] = p;
    j += k; if (j >= T) j -= T;
    j2 -= k; if (j2 < 0) j2 += T;
  }
}

// K5: combine scales with mlp weights
__global__ void k_comb(const float* __restrict__ mw) {
  int idx = blockIdx.x * 256 + threadIdx.x;
  if (idx >= 768 * 192) return;
  int jj = idx / 192, t = idx % 192;
  float acc = mw[2] * d_G[(size_t)(576 + jj) * 192 + t];
  if (jj >= 384) acc += mw[1] * d_G[(size_t)(192 + jj - 384) * 192 + t];
  if (jj >= 576) acc += mw[0] * d_G[(size_t)(jj - 576) * 192 + t];
  d_Gc[idx] = acc;
}

// K6: out[b,t,d] = mlp_b + sum_j inputs[b,j,d] * Gc[j,t]
__global__ void k_out(const float* __restrict__ inp, const float* __restrict__ mb, float* __restrict__ out) {
  __shared__ float fs[4096];
  int b = blockIdx.y, tt = blockIdx.x;
  int tid = threadIdx.x, d = tid & 63, tq = tid >> 6;
  float acc[4] = {0.f, 0.f, 0.f, 0.f};
  const float* ib = inp + (size_t)b * 768 * 64;
  for (int j0 = 0; j0 < 768; j0 += 64) {
    __syncthreads();
    for (int e = tid; e < 4096; e += 256) fs[e] = ib[(size_t)j0 * 64 + e];
    __syncthreads();
    for (int jj = 0; jj < 64; jj++) {
      float f = fs[jj * 64 + d];
#pragma unroll
      for (int l = 0; l < 4; l++) {
        int t = tt * 16 + tq * 4 + l;
        acc[l] += f * d_Gc[(size_t)(j0 + jj) * 192 + t];
      }
    }
  }
  float bb = mb[0];
#pragma unroll
  for (int l = 0; l < 4; l++) {
    int t = tt * 16 + tq * 4 + l;
    out[((size_t)b * 192 + t) * 64 + d] = acc[l] + bb;
  }
}

extern "C" void kernel_launch(void* const* d_in, const int* in_sizes, int n_in,
                              void* d_out, int out_size) {
  const float* inputs = (const float*)d_in[0];
  const float* spec_wr = (const float*)d_in[1];
  const float* spec_wi = (const float*)d_in[2];
  const float* mlp_w = (const float*)d_in[3];
  const float* mlp_b = (const float*)d_in[4];
  float* out = (float*)d_out;

  k_copy<<<256, 256>>>(h_tw, h_al, (const uint4*)h_HfH, (const uint4*)h_HfL,
                       (const uint4*)h_EfH, (const uint4*)h_EfL);
  k_w2<<<dim3(256, 3), 256>>>(spec_wr, spec_wi);
  k_gemmU<<<dim3(192, 7), 384>>>();
  k_chunksum<<<dim3(24, 21), 256>>>();
  k_coff<<<(21 * 6144 + 255) / 256, 256>>>();
  k_scanG<<<dim3(24, 21), 256>>>();
  k_comb<<<(768 * 192 + 255) / 256, 256>>>(mlp_w);
  k_out<<<dim3(12, 8), 256>>>(inputs, mlp_b, out);
}

// round 8
// speedup vs baseline: 1.7507x; 1.0566x over previous
#include <cuda_runtime.h>
#include <cuda_bf16.h>
#include <vector>
#include <cmath>
#include <cstring>

#define HID 256
#define OLEN 192
#define NMODE 32
#define TSUM 1344
#define NCOL 12288   // 192*32*2
#define NH4 (84 * 16 * 32)      // H-frag uint4 count
#define NE4 (3 * 12 * 16 * 32)  // em-frag uint4 count

// ---------------- host constant tables ----------------
static float h_H[TSUM * HID];
static float h_em[3 * OLEN * HID];
static float h_al[3 * NMODE * 2];
static unsigned h_HfH[NH4 * 4], h_HfL[NH4 * 4];
static unsigned h_EfH[NE4 * 4], h_EfL[NE4 * 4];

static inline unsigned short f2bf(float x) {
  unsigned u; memcpy(&u, &x, 4);
  return (unsigned short)((u + 0x7FFF + ((u >> 16) & 1)) >> 16);
}
static inline float bff(unsigned short b) {
  unsigned u = (unsigned)b << 16; float f; memcpy(&f, &u, 4); return f;
}
static inline void pack_pair(float e0, float e1, unsigned& hi, unsigned& lo) {
  unsigned short h0 = f2bf(e0), h1 = f2bf(e1);
  unsigned short l0 = f2bf(e0 - bff(h0)), l1 = f2bf(e1 - bff(h1));
  hi = ((unsigned)h1 << 16) | h0;
  lo = ((unsigned)l1 << 16) | l0;
}

struct HostInit {
  HostInit() {
    const double PI2 = 6.283185307179586476925286766559;
    for (int si = 0; si < 3; si++) {
      int sc = 1 << si;
      int T = OLEN * sc;
      int uoff = (si == 0) ? 0 : (si == 1) ? 192 : 576;
      double dt = 1.0 / (double)T;
      std::vector<double> M((size_t)HID * HID), R((size_t)HID * (HID + 1)), X((size_t)HID * (HID + 1));
      for (int r = 0; r < HID; r++) {
        for (int c = 0; c < HID; c++) {
          double a = (r < c) ? -1.0 : (((r - c) & 1) ? 1.0 : -1.0);
          a *= (2.0 * r + 1.0);
          M[(size_t)r * HID + c] = (r == c ? 1.0 : 0.0) - 0.5 * dt * a;
          R[(size_t)r * (HID + 1) + c] = (r == c ? 1.0 : 0.0) + 0.5 * dt * a;
        }
        R[(size_t)r * (HID + 1) + HID] = ((r & 1) ? -1.0 : 1.0) * (2.0 * r + 1.0) * dt;
      }
      for (int col = 0; col < HID; col++) {
        int piv = col; double mx = fabs(M[(size_t)col * HID + col]);
        for (int r = col + 1; r < HID; r++) { double v = fabs(M[(size_t)r * HID + col]); if (v > mx) { mx = v; piv = r; } }
        if (piv != col) {
          for (int c = col; c < HID; c++) { double t = M[(size_t)col*HID+c]; M[(size_t)col*HID+c] = M[(size_t)piv*HID+c]; M[(size_t)piv*HID+c] = t; }
          for (int c = 0; c <= HID; c++) { double t = R[(size_t)col*(HID+1)+c]; R[(size_t)col*(HID+1)+c] = R[(size_t)piv*(HID+1)+c]; R[(size_t)piv*(HID+1)+c] = t; }
        }
        double d = M[(size_t)col * HID + col];
        for (int r = col + 1; r < HID; r++) {
          double f = M[(size_t)r * HID + col] / d;
          if (f != 0.0) {
            for (int c = col; c < HID; c++) M[(size_t)r*HID+c] -= f * M[(size_t)col*HID+c];
            for (int c = 0; c <= HID; c++) R[(size_t)r*(HID+1)+c] -= f * R[(size_t)col*(HID+1)+c];
          }
        }
      }
      for (int r = HID - 1; r >= 0; r--) {
        double diag = M[(size_t)r * HID + r];
        for (int c = 0; c <= HID; c++) {
          double s = R[(size_t)r * (HID + 1) + c];
          for (int rr = r + 1; rr < HID; rr++) s -= M[(size_t)r*HID+rr] * X[(size_t)rr*(HID+1)+c];
          X[(size_t)r * (HID + 1) + c] = s / diag;
        }
      }
      std::vector<double> Ad((size_t)HID * HID), h(HID), hn(HID);
      for (int r = 0; r < HID; r++) {
        for (int c = 0; c < HID; c++) Ad[(size_t)r*HID+c] = (double)(float)X[(size_t)r*(HID+1)+c];
        h[r] = (double)(float)X[(size_t)r*(HID+1)+HID];
      }
      for (int u = 0; u < T; u++) {
        for (int i = 0; i < HID; i++) h_H[(size_t)(uoff + u) * HID + i] = (float)h[i];
        for (int i = 0; i < HID; i++) {
          double s = 0; const double* row = &Ad[(size_t)i * HID];
          for (int j = 0; j < HID; j++) s += row[j] * h[j];
          hn[i] = s;
        }
        h.swap(hn);
      }
      for (int t = 0; t < OLEN; t++) {
        int j = T - OLEN + t;
        double x = 1.0 - 2.0 * ((double)j * dt);
        float* dst = &h_em[((size_t)si * OLEN + t) * HID];
        double p0 = 1.0, p1 = x;
        dst[0] = (float)p0; dst[1] = (float)p1;
        for (int n = 1; n < HID - 1; n++) {
          double p2 = ((2.0*n+1.0)*x*p1 - (double)n*p0) / (double)(n+1);
          dst[n+1] = (float)p2; p0 = p1; p1 = p2;
        }
      }
      h_al[(si * NMODE + 0) * 2 + 0] = (float)(1.0 / (double)T);
      h_al[(si * NMODE + 0) * 2 + 1] = 0.0f;
      for (int k = 1; k < NMODE; k++) {
        double th = PI2 * (double)(191 * k) / (double)T;
        h_al[(si * NMODE + k) * 2 + 0] = (float)(2.0 / T * cos(th));
        h_al[(si * NMODE + k) * 2 + 1] = (float)(2.0 / T * sin(th));
      }
    }
    // H fragments in m16n8k16 A order (hi/lo bf16 pairs)
    for (int ut = 0; ut < 84; ut++)
      for (int mmg = 0; mmg < 16; mmg++)
        for (int lane = 0; lane < 32; lane++) {
          int r = lane >> 2, c = lane & 3;
          int r0 = ut * 16 + r, r1 = r0 + 8, i0 = mmg * 16;
          int idx = (((ut * 16) + mmg) * 32 + lane) * 4;
          pack_pair(h_H[(size_t)r0*256 + i0+2*c],   h_H[(size_t)r0*256 + i0+2*c+1], h_HfH[idx+0], h_HfL[idx+0]);
          pack_pair(h_H[(size_t)r1*256 + i0+2*c],   h_H[(size_t)r1*256 + i0+2*c+1], h_HfH[idx+1], h_HfL[idx+1]);
          pack_pair(h_H[(size_t)r0*256 + i0+2*c+8], h_H[(size_t)r0*256 + i0+2*c+9], h_HfH[idx+2], h_HfL[idx+2]);
          pack_pair(h_H[(size_t)r1*256 + i0+2*c+8], h_H[(size_t)r1*256 + i0+2*c+9], h_HfH[idx+3], h_HfL[idx+3]);
        }
    // em fragments
    for (int s = 0; s < 3; s++)
      for (int mt = 0; mt < 12; mt++)
        for (int mmg = 0; mmg < 16; mmg++)
          for (int lane = 0; lane < 32; lane++) {
            int r = lane >> 2, c = lane & 3;
            int r0 = mt * 16 + r, r1 = r0 + 8, o0 = mmg * 16;
            const float* A = h_em + (size_t)s * 192 * 256;
            int idx = ((((s * 12 + mt) * 16) + mmg) * 32 + lane) * 4;
            pack_pair(A[(size_t)r0*256 + o0+2*c],   A[(size_t)r0*256 + o0+2*c+1], h_EfH[idx+0], h_EfL[idx+0]);
            pack_pair(A[(size_t)r1*256 + o0+2*c],   A[(size_t)r1*256 + o0+2*c+1], h_EfH[idx+1], h_EfL[idx+1]);
            pack_pair(A[(size_t)r0*256 + o0+2*c+8], A[(size_t)r0*256 + o0+2*c+9], h_EfH[idx+2], h_EfL[idx+2]);
            pack_pair(A[(size_t)r1*256 + o0+2*c+8], A[(size_t)r1*256 + o0+2*c+9], h_EfH[idx+3], h_EfL[idx+3]);
          }
  }
};
static HostInit g_init;

// ---------------- device scratch ----------------
__device__ uint4 d_HfH[NH4], d_HfL[NH4];
__device__ uint4 d_EfH[NE4], d_EfL[NE4];
__device__ __nv_bfloat16 d_W2h[3 * 256 * NCOL];
__device__ __nv_bfloat16 d_W2l[3 * 256 * NCOL];
__device__ float d_Bs[7 * 192 * 32 * 2];   // per-block chunk sums (complex)
__device__ float d_G[TSUM * 192];
__device__ float d_Gc[768 * 192];
__device__ float d_ald[3 * 32 * 2];

__device__ __forceinline__ void mma16(float4& d, const uint4& a, unsigned b0, unsigned b1) {
  asm("mma.sync.aligned.m16n8k16.row.col.f32.bf16.bf16.f32 "
      "{%0,%1,%2,%3},{%4,%5,%6,%7},{%8,%9},{%0,%1,%2,%3};"
      : "+f"(d.x), "+f"(d.y), "+f"(d.z), "+f"(d.w)
      : "r"(a.x), "r"(a.y), "r"(a.z), "r"(a.w), "r"(b0), "r"(b1));
}

__device__ __forceinline__ unsigned pkbf(float a, float b) {
  __nv_bfloat16 ha = __float2bfloat16_rn(a), hb = __float2bfloat16_rn(b);
  return ((unsigned)__bfloat16_as_ushort(hb) << 16) | __bfloat16_as_ushort(ha);
}

// inclusive segmented scan over r (= lane>>2), 8 segments of stride 4
__device__ __forceinline__ float scan_r(float v, int r) {
  float t;
  t = __shfl_up_sync(0xffffffffu, v, 4);  v += (r >= 1) ? t : 0.f;
  t = __shfl_up_sync(0xffffffffu, v, 8);  v += (r >= 2) ? t : 0.f;
  t = __shfl_up_sync(0xffffffffu, v, 16); v += (r >= 4) ? t : 0.f;
  return v;
}

// K0: pull host constants via ATS (GB300 C2C)
__global__ void k_copy(const float* __restrict__ hal,
                       const uint4* __restrict__ hHfH, const uint4* __restrict__ hHfL,
                       const uint4* __restrict__ hEfH, const uint4* __restrict__ hEfL) {
  int i = blockIdx.x * blockDim.x + threadIdx.x, st = gridDim.x * blockDim.x;
  for (int j = i; j < 3 * 32 * 2; j += st) d_ald[j] = hal[j];
  for (int j = i; j < NH4; j += st) { d_HfH[j] = hHfH[j]; d_HfL[j] = hHfL[j]; }
  for (int j = i; j < NE4; j += st) { d_EfH[j] = hEfH[j]; d_EfL[j] = hEfL[j]; }
}

// K1: W2[s][i][t][2k+reim] = alpha_k * sum_o w[s,i,o,k] * em[s,t,o]
// bf16 m16n8k16, 3-pass split. Block = (i, s): C[192 x 64], K = 256 (o).
__global__ void k_w2(const float* __restrict__ wr, const float* __restrict__ wi) {
  __shared__ unsigned Bph[16 * 72], Bpl[16 * 72];
  int s = blockIdx.y, i = blockIdx.x;
  int tid = threadIdx.x, wid = tid >> 5, lane = tid & 31;
  int whalf = wid & 1, wg = wid >> 1;
  int r = lane >> 2, c = lane & 3;
  const float* wrb = wr + (size_t)(s * 256 + i) * 8192;
  const float* wib = wi + (size_t)(s * 256 + i) * 8192;
  float4 acc[3][4];
#pragma unroll
  for (int mt = 0; mt < 3; mt++)
#pragma unroll
    for (int j = 0; j < 4; j++) acc[mt][j] = make_float4(0.f, 0.f, 0.f, 0.f);
  int o2s = tid >> 4, kp = tid & 15;

  for (int ch = 0; ch < 8; ch++) {
    __syncthreads();
    {  // stage 32 o rows as paired bf16 hi/lo
      int oa = ch * 32 + 2 * o2s;
      float2 ra = *(const float2*)(wrb + (size_t)oa * 32 + 2 * kp);
      float2 rb = *(const float2*)(wrb + (size_t)(oa + 1) * 32 + 2 * kp);
      float2 ia = *(const float2*)(wib + (size_t)oa * 32 + 2 * kp);
      float2 ib = *(const float2*)(wib + (size_t)(oa + 1) * 32 + 2 * kp);
      float va[4] = {ra.x, ia.x, ra.y, ia.y};
      float vb[4] = {rb.x, ib.x, rb.y, ib.y};
#pragma unroll
      for (int e = 0; e < 4; e++) {
        int n = 4 * kp + e;
        int p = o2s * 72 + (n & 7) * 8 + (n >> 3);
        __nv_bfloat16 ha = __float2bfloat16_rn(va[e]), hb = __float2bfloat16_rn(vb[e]);
        Bph[p] = ((unsigned)__bfloat16_as_ushort(hb) << 16) | __bfloat16_as_ushort(ha);
        Bpl[p] = pkbf(va[e] - __bfloat162float(ha), vb[e] - __bfloat162float(hb));
      }
    }
    __syncthreads();
#pragma unroll
    for (int m = 0; m < 2; m++) {
      uint4 b0h = *(const uint4*)&Bph[(8 * m + c) * 72 + r * 8 + whalf * 4];
      uint4 b1h = *(const uint4*)&Bph[(8 * m + c + 4) * 72 + r * 8 + whalf * 4];
      uint4 b0l = *(const uint4*)&Bpl[(8 * m + c) * 72 + r * 8 + whalf * 4];
      uint4 b1l = *(const uint4*)&Bpl[(8 * m + c + 4) * 72 + r * 8 + whalf * 4];
      const unsigned* p0h = (const unsigned*)&b0h;
      const unsigned* p1h = (const unsigned*)&b1h;
      const unsigned* p0l = (const unsigned*)&b0l;
      const unsigned* p1l = (const unsigned*)&b1l;
      int mmg = ch * 2 + m;
#pragma unroll
      for (int mt = 0; mt < 3; mt++) {
        int mtile = wg * 3 + mt;
        uint4 ah = d_EfH[((s * 12 + mtile) * 16 + mmg) * 32 + lane];
        uint4 al = d_EfL[((s * 12 + mtile) * 16 + mmg) * 32 + lane];
#pragma unroll
        for (int j = 0; j < 4; j++) {
          mma16(acc[mt][j], ah, p0h[j], p1h[j]);
          mma16(acc[mt][j], ah, p0l[j], p1l[j]);
          mma16(acc[mt][j], al, p0h[j], p1h[j]);
        }
      }
    }
  }
  // epilogue: alpha-scale (complex), store bf16 hi/lo planes
  size_t base0 = (size_t)(s * 256 + i) * NCOL;
#pragma unroll
  for (int mt = 0; mt < 3; mt++) {
#pragma unroll
    for (int j = 0; j < 4; j++) {
      int ncol = whalf * 32 + j * 8 + 2 * c;
      int kmode = ncol >> 1;
      float alr = d_ald[(s * 32 + kmode) * 2], ali = d_ald[(s * 32 + kmode) * 2 + 1];
      float4 cv = acc[mt][j];
      int t0 = wg * 48 + mt * 16 + r;
      float re0 = alr * cv.x - ali * cv.y, im0 = alr * cv.y + ali * cv.x;
      float re1 = alr * cv.z - ali * cv.w, im1 = alr * cv.w + ali * cv.z;
      size_t e0 = base0 + (size_t)t0 * 64 + ncol;
      size_t e1 = base0 + (size_t)(t0 + 8) * 64 + ncol;
      __nv_bfloat16 h0r = __float2bfloat16_rn(re0), h0i = __float2bfloat16_rn(im0);
      __nv_bfloat16 h1r = __float2bfloat16_rn(re1), h1i = __float2bfloat16_rn(im1);
      *(unsigned*)(d_W2h + e0) = ((unsigned)__bfloat16_as_ushort(h0i) << 16) | __bfloat16_as_ushort(h0r);
      *(unsigned*)(d_W2h + e1) = ((unsigned)__bfloat16_as_ushort(h1i) << 16) | __bfloat16_as_ushort(h1r);
      *(unsigned*)(d_W2l + e0) = pkbf(re0 - __bfloat162float(h0r), im0 - __bfloat162float(h0i));
      *(unsigned*)(d_W2l + e1) = pkbf(re1 - __bfloat162float(h1r), im1 - __bfloat162float(h1i));
    }
  }
}

// K2: U[u, n] = sum_i H[u,i] * W2[s(u)][i, n]  (bf16 3-pass) FUSED with
// twiddle-multiply, prefix over u, and k-reduction into G (block bn = one t).
__global__ void k_gemmU() {
  __shared__ unsigned Bph[16 * 72], Bpl[16 * 72];
  __shared__ float WsRe[12][32], WsIm[12][32];
  int bn = blockIdx.x, ub = blockIdx.y;
  int s = (ub == 0) ? 0 : (ub < 3) ? 1 : 2;
  int tid = threadIdx.x, wid = tid >> 5, lane = tid & 31;
  int r = lane >> 2, c = lane & 3;
  int ut = ub * 12 + wid;
  float4 acc[8];
#pragma unroll
  for (int j = 0; j < 8; j++) acc[j] = make_float4(0.f, 0.f, 0.f, 0.f);

  for (int ch = 0; ch < 8; ch++) {
    __syncthreads();
    if (tid < 256) {  // stage: pair consecutive-i rows of W2h/W2l
      int pairsel = tid >> 7, t2 = tid & 127;
      int k2 = t2 >> 3, oc = t2 & 7;
      const __nv_bfloat16* base = pairsel ? d_W2l : d_W2h;
      const __nv_bfloat16* src = base + (size_t)(s * 256 + ch * 32 + 2 * k2) * NCOL + bn * 64 + oc * 8;
      uint4 va = *(const uint4*)src;
      uint4 vb = *(const uint4*)(src + NCOL);
      unsigned* dst = pairsel ? Bpl : Bph;
      const unsigned* pa = (const unsigned*)&va;
      const unsigned* pb = (const unsigned*)&vb;
#pragma unroll
      for (int h2 = 0; h2 < 4; h2++) {
        int n0 = oc * 8 + h2 * 2, n1 = n0 + 1;
        dst[k2 * 72 + (n0 & 7) * 8 + (n0 >> 3)] = __byte_perm(pa[h2], pb[h2], 0x5410);
        dst[k2 * 72 + (n1 & 7) * 8 + (n1 >> 3)] = __byte_perm(pa[h2], pb[h2], 0x7632);
      }
    }
    __syncthreads();
#pragma unroll
    for (int m = 0; m < 2; m++) {
      int mmg = ch * 2 + m;
      uint4 ah = d_HfH[(ut * 16 + mmg) * 32 + lane];
      uint4 al = d_HfL[(ut * 16 + mmg) * 32 + lane];
#pragma unroll
      for (int half = 0; half < 2; half++) {
        uint4 b0h = *(const uint4*)&Bph[(8 * m + c) * 72 + r * 8 + half * 4];
        uint4 b1h = *(const uint4*)&Bph[(8 * m + c + 4) * 72 + r * 8 + half * 4];
        uint4 b0l = *(const uint4*)&Bpl[(8 * m + c) * 72 + r * 8 + half * 4];
        uint4 b1l = *(const uint4*)&Bpl[(8 * m + c + 4) * 72 + r * 8 + half * 4];
        const unsigned* p0h = (const unsigned*)&b0h;
        const unsigned* p1h = (const unsigned*)&b1h;
        const unsigned* p0l = (const unsigned*)&b0l;
        const unsigned* p1l = (const unsigned*)&b1l;
#pragma unroll
        for (int j = 0; j < 4; j++) {
          int jj = half * 4 + j;
          mma16(acc[jj], ah, p0h[j], p1h[j]);
          mma16(acc[jj], ah, p0l[j], p1l[j]);
          mma16(acc[jj], al, p0h[j], p1h[j]);
        }
      }
    }
  }
  // ---------- fused scan epilogue ----------
  // acc[j]: u0 = warp*16 + r (x=re,y=im), u1 = u0 + 8 (z=re,w=im); k = j*4 + c
  int T = 192 << s;
  int uoff = (s == 0) ? 0 : (s == 1) ? 192 : 576;
  int ul0 = ub * 192 - uoff + wid * 16;   // local-in-scale u of row r
  float pi2t = 6.2831853071795864f / (float)T;
  // 1) twiddle-multiply in place: V = e^{-i*2pi*u*k/T} * U
#pragma unroll
  for (int j = 0; j < 8; j++) {
    int k = j * 4 + c;
    int u0 = ul0 + r, u1 = u0 + 8;
    float s0, c0, s1, c1;
    __sincosf(pi2t * (float)((u0 * k) % T), &s0, &c0);
    __sincosf(pi2t * (float)((u1 * k) % T), &s1, &c1);
    float re0 = c0 * acc[j].x + s0 * acc[j].y;
    float im0 = c0 * acc[j].y - s0 * acc[j].x;
    float re1 = c1 * acc[j].z + s1 * acc[j].w;
    float im1 = c1 * acc[j].w - s1 * acc[j].z;
    acc[j].x = re0; acc[j].y = im0; acc[j].z = re1; acc[j].w = im1;
  }
  // 2) intra-warp inclusive prefix over u (16 rows)
#pragma unroll
  for (int j = 0; j < 8; j++) {
    acc[j].x = scan_r(acc[j].x, r);
    acc[j].y = scan_r(acc[j].y, r);
    float t0re = __shfl_sync(0xffffffffu, acc[j].x, 28 + c);
    float t0im = __shfl_sync(0xffffffffu, acc[j].y, 28 + c);
    acc[j].z = scan_r(acc[j].z, r) + t0re;
    acc[j].w = scan_r(acc[j].w, r) + t0im;
  }
  // 3) cross-warp exclusive prefix of warp totals
  if (r == 7) {
#pragma unroll
    for (int j = 0; j < 8; j++) { WsRe[wid][j * 4 + c] = acc[j].z; WsIm[wid][j * 4 + c] = acc[j].w; }
  }
  __syncthreads();
  if (wid == 0) {
    float runr = 0.f, runi = 0.f;
#pragma unroll
    for (int w = 0; w < 12; w++) {
      float tr = WsRe[w][lane], ti = WsIm[w][lane];
      WsRe[w][lane] = runr; WsIm[w][lane] = runi;
      runr += tr; runi += ti;
    }
    ((float2*)d_Bs)[(ub * 192 + bn) * 32 + lane] = make_float2(runr, runi);
  }
  __syncthreads();
  // 4) add warp seed, reduce over k into Glocal, write d_G
  float g0 = 0.f, g1 = 0.f;
#pragma unroll
  for (int j = 0; j < 8; j++) {
    int k = j * 4 + c;
    float wre = WsRe[wid][k], wim = WsIm[wid][k];
    float pre0 = acc[j].x + wre, pim0 = acc[j].y + wim;
    float pre1 = acc[j].z + wre, pim1 = acc[j].w + wim;
    int m0 = ul0 + r, m1 = m0 + 8;
    int tau0 = T - 1 - m0, tau1 = T - 1 - m1;
    float sa, ca, sb, cb;
    __sincosf(pi2t * (float)((tau0 * k) % T), &sa, &ca);
    __sincosf(pi2t * (float)((tau1 * k) % T), &sb, &cb);
    g0 += ca * pre0 + sa * pim0;
    g1 += cb * pre1 + sb * pim1;
  }
  g0 += __shfl_xor_sync(0xffffffffu, g0, 1);
  g0 += __shfl_xor_sync(0xffffffffu, g0, 2);
  g1 += __shfl_xor_sync(0xffffffffu, g1, 1);
  g1 += __shfl_xor_sync(0xffffffffu, g1, 2);
  if (c == 0) {
    int m0 = ul0 + r;
    d_G[(size_t)(uoff + T - 1 - m0) * 192 + bn] = g0;
    d_G[(size_t)(uoff + T - 1 - (m0 + 8)) * 192 + bn] = g1;
  }
}

// K3: add cross-block prefix seeds into G (rows whose m is in a later 192-block)
__global__ void k_fix() {
  int gw = (blockIdx.x * 256 + threadIdx.x) >> 5;
  int lane = threadIdx.x & 31;
  if (gw >= 768 * 192) return;
  int r768 = gw / 192, t = gw % 192;
  int tau, uoff, T, ubbase;
  if (r768 < 192) { tau = r768; uoff = 192; T = 384; ubbase = 1; }
  else { tau = r768 - 192; uoff = 576; T = 768; ubbase = 3; }
  int m = T - 1 - tau;
  int lb = m / 192;          // >= 1 by construction
  float cor = 0.f, coi = 0.f;
  for (int x = 0; x < lb; x++) {
    float2 v = ((const float2*)d_Bs)[((ubbase + x) * 192 + t) * 32 + lane];
    cor += v.x; coi += v.y;
  }
  float sn, cs;
  __sincosf((6.2831853071795864f / (float)T) * (float)((tau * lane) % T), &sn, &cs);
  float g = cs * cor + sn * coi;
#pragma unroll
  for (int off = 16; off; off >>= 1) g += __shfl_xor_sync(0xffffffffu, g, off);
  if (!lane) d_G[(size_t)(uoff + tau) * 192 + t] += g;
}

// K5: combine scales with mlp weights
__global__ void k_comb(const float* __restrict__ mw) {
  int idx = blockIdx.x * 256 + threadIdx.x;
  if (idx >= 768 * 192) return;
  int jj = idx / 192, t = idx % 192;
  float acc = mw[2] * d_G[(size_t)(576 + jj) * 192 + t];
  if (jj >= 384) acc += mw[1] * d_G[(size_t)(192 + jj - 384) * 192 + t];
  if (jj >= 576) acc += mw[0] * d_G[(size_t)(jj - 576) * 192 + t];
  d_Gc[idx] = acc;
}

// K6: out[b,t,d] = mlp_b + sum_j inputs[b,j,d] * Gc[j,t]
__global__ void k_out(const float* __restrict__ inp, const float* __restrict__ mb, float* __restrict__ out) {
  __shared__ float fs[4096];
  int b = blockIdx.y, tt = blockIdx.x;
  int tid = threadIdx.x, d = tid & 63, tq = tid >> 6;
  float acc[4] = {0.f, 0.f, 0.f, 0.f};
  const float* ib = inp + (size_t)b * 768 * 64;
  for (int j0 = 0; j0 < 768; j0 += 64) {
    __syncthreads();
    for (int e = tid; e < 4096; e += 256) fs[e] = ib[(size_t)j0 * 64 + e];
    __syncthreads();
    for (int jj = 0; jj < 64; jj++) {
      float f = fs[jj * 64 + d];
#pragma unroll
      for (int l = 0; l < 4; l++) {
        int t = tt * 16 + tq * 4 + l;
        acc[l] += f * d_Gc[(size_t)(j0 + jj) * 192 + t];
      }
    }
  }
  float bb = mb[0];
#pragma unroll
  for (int l = 0; l < 4; l++) {
    int t = tt * 16 + tq * 4 + l;
    out[((size_t)b * 192 + t) * 64 + d] = acc[l] + bb;
  }
}

extern "C" void kernel_launch(void* const* d_in, const int* in_sizes, int n_in,
                              void* d_out, int out_size) {
  const float* inputs = (const float*)d_in[0];
  const float* spec_wr = (const float*)d_in[1];
  const float* spec_wi = (const float*)d_in[2];
  const float* mlp_w = (const float*)d_in[3];
  const float* mlp_b = (const float*)d_in[4];
  float* out = (float*)d_out;

  k_copy<<<256, 256>>>(h_al, (const uint4*)h_HfH, (const uint4*)h_HfL,
                       (const uint4*)h_EfH, (const uint4*)h_EfL);
  k_w2<<<dim3(256, 3), 256>>>(spec_wr, spec_wi);
  k_gemmU<<<dim3(192, 7), 384>>>();
  k_fix<<<(768 * 192 * 32 + 255) / 256, 256>>>();
  k_comb<<<(768 * 192 + 255) / 256, 256>>>(mlp_w);
  k_out<<<dim3(12, 8), 256>>>(inputs, mlp_b, out);
}

// round 9
// speedup vs baseline: 1.8383x; 1.0500x over previous
#include <cuda_runtime.h>
#include <cuda_bf16.h>
#include <vector>
#include <cmath>
#include <cstring>

#define HID 256
#define OLEN 192
#define NMODE 32
#define TSUM 1344
#define NCOL 12288   // 192*32*2
#define NH4 (84 * 16 * 32)      // H-frag uint4 count
#define NE4 (3 * 12 * 16 * 32)  // em-frag uint4 count

// ---------------- host constant tables ----------------
static float h_H[TSUM * HID];
static float h_em[3 * OLEN * HID];
static float h_al[3 * NMODE * 2];
static unsigned h_HfH[NH4 * 4], h_HfL[NH4 * 4];
static unsigned h_EfH[NE4 * 4], h_EfL[NE4 * 4];

static inline unsigned short f2bf(float x) {
  unsigned u; memcpy(&u, &x, 4);
  return (unsigned short)((u + 0x7FFF + ((u >> 16) & 1)) >> 16);
}
static inline float bff(unsigned short b) {
  unsigned u = (unsigned)b << 16; float f; memcpy(&f, &u, 4); return f;
}
static inline void pack_pair(float e0, float e1, unsigned& hi, unsigned& lo) {
  unsigned short h0 = f2bf(e0), h1 = f2bf(e1);
  unsigned short l0 = f2bf(e0 - bff(h0)), l1 = f2bf(e1 - bff(h1));
  hi = ((unsigned)h1 << 16) | h0;
  lo = ((unsigned)l1 << 16) | l0;
}

struct HostInit {
  HostInit() {
    const double PI2 = 6.283185307179586476925286766559;
    for (int si = 0; si < 3; si++) {
      int sc = 1 << si;
      int T = OLEN * sc;
      int uoff = (si == 0) ? 0 : (si == 1) ? 192 : 576;
      double dt = 1.0 / (double)T;
      std::vector<double> M((size_t)HID * HID), R((size_t)HID * (HID + 1)), X((size_t)HID * (HID + 1));
      for (int r = 0; r < HID; r++) {
        for (int c = 0; c < HID; c++) {
          double a = (r < c) ? -1.0 : (((r - c) & 1) ? 1.0 : -1.0);
          a *= (2.0 * r + 1.0);
          M[(size_t)r * HID + c] = (r == c ? 1.0 : 0.0) - 0.5 * dt * a;
          R[(size_t)r * (HID + 1) + c] = (r == c ? 1.0 : 0.0) + 0.5 * dt * a;
        }
        R[(size_t)r * (HID + 1) + HID] = ((r & 1) ? -1.0 : 1.0) * (2.0 * r + 1.0) * dt;
      }
      for (int col = 0; col < HID; col++) {
        int piv = col; double mx = fabs(M[(size_t)col * HID + col]);
        for (int r = col + 1; r < HID; r++) { double v = fabs(M[(size_t)r * HID + col]); if (v > mx) { mx = v; piv = r; } }
        if (piv != col) {
          for (int c = col; c < HID; c++) { double t = M[(size_t)col*HID+c]; M[(size_t)col*HID+c] = M[(size_t)piv*HID+c]; M[(size_t)piv*HID+c] = t; }
          for (int c = 0; c <= HID; c++) { double t = R[(size_t)col*(HID+1)+c]; R[(size_t)col*(HID+1)+c] = R[(size_t)piv*(HID+1)+c]; R[(size_t)piv*(HID+1)+c] = t; }
        }
        double d = M[(size_t)col * HID + col];
        for (int r = col + 1; r < HID; r++) {
          double f = M[(size_t)r * HID + col] / d;
          if (f != 0.0) {
            for (int c = col; c < HID; c++) M[(size_t)r*HID+c] -= f * M[(size_t)col*HID+c];
            for (int c = 0; c <= HID; c++) R[(size_t)r*(HID+1)+c] -= f * R[(size_t)col*(HID+1)+c];
          }
        }
      }
      for (int r = HID - 1; r >= 0; r--) {
        double diag = M[(size_t)r * HID + r];
        for (int c = 0; c <= HID; c++) {
          double s = R[(size_t)r * (HID + 1) + c];
          for (int rr = r + 1; rr < HID; rr++) s -= M[(size_t)r*HID+rr] * X[(size_t)rr*(HID+1)+c];
          X[(size_t)r * (HID + 1) + c] = s / diag;
        }
      }
      std::vector<double> Ad((size_t)HID * HID), h(HID), hn(HID);
      for (int r = 0; r < HID; r++) {
        for (int c = 0; c < HID; c++) Ad[(size_t)r*HID+c] = (double)(float)X[(size_t)r*(HID+1)+c];
        h[r] = (double)(float)X[(size_t)r*(HID+1)+HID];
      }
      for (int u = 0; u < T; u++) {
        for (int i = 0; i < HID; i++) h_H[(size_t)(uoff + u) * HID + i] = (float)h[i];
        for (int i = 0; i < HID; i++) {
          double s = 0; const double* row = &Ad[(size_t)i * HID];
          for (int j = 0; j < HID; j++) s += row[j] * h[j];
          hn[i] = s;
        }
        h.swap(hn);
      }
      for (int t = 0; t < OLEN; t++) {
        int j = T - OLEN + t;
        double x = 1.0 - 2.0 * ((double)j * dt);
        float* dst = &h_em[((size_t)si * OLEN + t) * HID];
        double p0 = 1.0, p1 = x;
        dst[0] = (float)p0; dst[1] = (float)p1;
        for (int n = 1; n < HID - 1; n++) {
          double p2 = ((2.0*n+1.0)*x*p1 - (double)n*p0) / (double)(n+1);
          dst[n+1] = (float)p2; p0 = p1; p1 = p2;
        }
      }
      h_al[(si * NMODE + 0) * 2 + 0] = (float)(1.0 / (double)T);
      h_al[(si * NMODE + 0) * 2 + 1] = 0.0f;
      for (int k = 1; k < NMODE; k++) {
        double th = PI2 * (double)(191 * k) / (double)T;
        h_al[(si * NMODE + k) * 2 + 0] = (float)(2.0 / T * cos(th));
        h_al[(si * NMODE + k) * 2 + 1] = (float)(2.0 / T * sin(th));
      }
    }
    for (int ut = 0; ut < 84; ut++)
      for (int mmg = 0; mmg < 16; mmg++)
        for (int lane = 0; lane < 32; lane++) {
          int r = lane >> 2, c = lane & 3;
          int r0 = ut * 16 + r, r1 = r0 + 8, i0 = mmg * 16;
          int idx = (((ut * 16) + mmg) * 32 + lane) * 4;
          pack_pair(h_H[(size_t)r0*256 + i0+2*c],   h_H[(size_t)r0*256 + i0+2*c+1], h_HfH[idx+0], h_HfL[idx+0]);
          pack_pair(h_H[(size_t)r1*256 + i0+2*c],   h_H[(size_t)r1*256 + i0+2*c+1], h_HfH[idx+1], h_HfL[idx+1]);
          pack_pair(h_H[(size_t)r0*256 + i0+2*c+8], h_H[(size_t)r0*256 + i0+2*c+9], h_HfH[idx+2], h_HfL[idx+2]);
          pack_pair(h_H[(size_t)r1*256 + i0+2*c+8], h_H[(size_t)r1*256 + i0+2*c+9], h_HfH[idx+3], h_HfL[idx+3]);
        }
    for (int s = 0; s < 3; s++)
      for (int mt = 0; mt < 12; mt++)
        for (int mmg = 0; mmg < 16; mmg++)
          for (int lane = 0; lane < 32; lane++) {
            int r = lane >> 2, c = lane & 3;
            int r0 = mt * 16 + r, r1 = r0 + 8, o0 = mmg * 16;
            const float* A = h_em + (size_t)s * 192 * 256;
            int idx = ((((s * 12 + mt) * 16) + mmg) * 32 + lane) * 4;
            pack_pair(A[(size_t)r0*256 + o0+2*c],   A[(size_t)r0*256 + o0+2*c+1], h_EfH[idx+0], h_EfL[idx+0]);
            pack_pair(A[(size_t)r1*256 + o0+2*c],   A[(size_t)r1*256 + o0+2*c+1], h_EfH[idx+1], h_EfL[idx+1]);
            pack_pair(A[(size_t)r0*256 + o0+2*c+8], A[(size_t)r0*256 + o0+2*c+9], h_EfH[idx+2], h_EfL[idx+2]);
            pack_pair(A[(size_t)r1*256 + o0+2*c+8], A[(size_t)r1*256 + o0+2*c+9], h_EfH[idx+3], h_EfL[idx+3]);
          }
  }
};
static HostInit g_init;

// ---------------- device scratch ----------------
__device__ uint4 d_HfH[NH4], d_HfL[NH4];
__device__ uint4 d_EfH[NE4], d_EfL[NE4];
__device__ __nv_bfloat16 d_W2h[3 * 256 * NCOL];
__device__ __nv_bfloat16 d_W2l[3 * 256 * NCOL];
__device__ float d_Bs[7 * 192 * 32 * 2];
__device__ float d_G[TSUM * 192];
__device__ float d_Gc[768 * 192];
__device__ float d_ald[3 * 32 * 2];

__device__ __forceinline__ void mma16(float4& d, const uint4& a, unsigned b0, unsigned b1) {
  asm("mma.sync.aligned.m16n8k16.row.col.f32.bf16.bf16.f32 "
      "{%0,%1,%2,%3},{%4,%5,%6,%7},{%8,%9},{%0,%1,%2,%3};"
      : "+f"(d.x), "+f"(d.y), "+f"(d.z), "+f"(d.w)
      : "r"(a.x), "r"(a.y), "r"(a.z), "r"(a.w), "r"(b0), "r"(b1));
}

__device__ __forceinline__ unsigned pkbf(float a, float b) {
  __nv_bfloat16 ha = __float2bfloat16_rn(a), hb = __float2bfloat16_rn(b);
  return ((unsigned)__bfloat16_as_ushort(hb) << 16) | __bfloat16_as_ushort(ha);
}

__device__ __forceinline__ float scan_r(float v, int r) {
  float t;
  t = __shfl_up_sync(0xffffffffu, v, 4);  v += (r >= 1) ? t : 0.f;
  t = __shfl_up_sync(0xffffffffu, v, 8);  v += (r >= 2) ? t : 0.f;
  t = __shfl_up_sync(0xffffffffu, v, 16); v += (r >= 4) ? t : 0.f;
  return v;
}

// K0: pull host constants via ATS (GB300 C2C)
__global__ void k_copy(const float* __restrict__ hal,
                       const uint4* __restrict__ hHfH, const uint4* __restrict__ hHfL,
                       const uint4* __restrict__ hEfH, const uint4* __restrict__ hEfL) {
  int i = blockIdx.x * blockDim.x + threadIdx.x, st = gridDim.x * blockDim.x;
  for (int j = i; j < 3 * 32 * 2; j += st) d_ald[j] = hal[j];
  for (int j = i; j < NH4; j += st) { d_HfH[j] = hHfH[j]; d_HfL[j] = hHfL[j]; }
  for (int j = i; j < NE4; j += st) { d_EfH[j] = hEfH[j]; d_EfL[j] = hEfL[j]; }
}

// K1: W2 = alpha .* (em @ Wc). bf16 3-pass, double-buffered staging.
__global__ void k_w2(const float* __restrict__ wr, const float* __restrict__ wi) {
  __shared__ unsigned Bph[2][16 * 72], Bpl[2][16 * 72];
  int s = blockIdx.y, i = blockIdx.x;
  int tid = threadIdx.x, wid = tid >> 5, lane = tid & 31;
  int whalf = wid & 1, wg = wid >> 1;
  int r = lane >> 2, c = lane & 3;
  const float* wrb = wr + (size_t)(s * 256 + i) * 8192;
  const float* wib = wi + (size_t)(s * 256 + i) * 8192;
  float4 acc[3][4];
#pragma unroll
  for (int mt = 0; mt < 3; mt++)
#pragma unroll
    for (int j = 0; j < 4; j++) acc[mt][j] = make_float4(0.f, 0.f, 0.f, 0.f);
  int o2s = tid >> 4, kp = tid & 15;

  float2 ra, rb, ia, ib;
  {
    int oa = 2 * o2s;
    ra = *(const float2*)(wrb + (size_t)oa * 32 + 2 * kp);
    rb = *(const float2*)(wrb + (size_t)(oa + 1) * 32 + 2 * kp);
    ia = *(const float2*)(wib + (size_t)oa * 32 + 2 * kp);
    ib = *(const float2*)(wib + (size_t)(oa + 1) * 32 + 2 * kp);
  }
  for (int ch = 0; ch < 8; ch++) {
    int bsel = ch & 1;
    {  // store prefetched regs to smem buffer
      float va[4] = {ra.x, ia.x, ra.y, ia.y};
      float vb[4] = {rb.x, ib.x, rb.y, ib.y};
#pragma unroll
      for (int e = 0; e < 4; e++) {
        int n = 4 * kp + e;
        int p = o2s * 72 + (n & 7) * 8 + (n >> 3);
        __nv_bfloat16 ha = __float2bfloat16_rn(va[e]), hb = __float2bfloat16_rn(vb[e]);
        Bph[bsel][p] = ((unsigned)__bfloat16_as_ushort(hb) << 16) | __bfloat16_as_ushort(ha);
        Bpl[bsel][p] = pkbf(va[e] - __bfloat162float(ha), vb[e] - __bfloat162float(hb));
      }
    }
    __syncthreads();
    if (ch < 7) {  // prefetch next chunk
      int oa = (ch + 1) * 32 + 2 * o2s;
      ra = *(const float2*)(wrb + (size_t)oa * 32 + 2 * kp);
      rb = *(const float2*)(wrb + (size_t)(oa + 1) * 32 + 2 * kp);
      ia = *(const float2*)(wib + (size_t)oa * 32 + 2 * kp);
      ib = *(const float2*)(wib + (size_t)(oa + 1) * 32 + 2 * kp);
    }
#pragma unroll
    for (int m = 0; m < 2; m++) {
      uint4 b0h = *(const uint4*)&Bph[bsel][(8 * m + c) * 72 + r * 8 + whalf * 4];
      uint4 b1h = *(const uint4*)&Bph[bsel][(8 * m + c + 4) * 72 + r * 8 + whalf * 4];
      uint4 b0l = *(const uint4*)&Bpl[bsel][(8 * m + c) * 72 + r * 8 + whalf * 4];
      uint4 b1l = *(const uint4*)&Bpl[bsel][(8 * m + c + 4) * 72 + r * 8 + whalf * 4];
      const unsigned* p0h = (const unsigned*)&b0h;
      const unsigned* p1h = (const unsigned*)&b1h;
      const unsigned* p0l = (const unsigned*)&b0l;
      const unsigned* p1l = (const unsigned*)&b1l;
      int mmg = ch * 2 + m;
#pragma unroll
      for (int mt = 0; mt < 3; mt++) {
        int mtile = wg * 3 + mt;
        uint4 ah = d_EfH[((s * 12 + mtile) * 16 + mmg) * 32 + lane];
        uint4 al = d_EfL[((s * 12 + mtile) * 16 + mmg) * 32 + lane];
#pragma unroll
        for (int j = 0; j < 4; j++) {
          mma16(acc[mt][j], ah, p0h[j], p1h[j]);
          mma16(acc[mt][j], ah, p0l[j], p1l[j]);
          mma16(acc[mt][j], al, p0h[j], p1h[j]);
        }
      }
    }
  }
  size_t base0 = (size_t)(s * 256 + i) * NCOL;
#pragma unroll
  for (int mt = 0; mt < 3; mt++) {
#pragma unroll
    for (int j = 0; j < 4; j++) {
      int ncol = whalf * 32 + j * 8 + 2 * c;
      int kmode = ncol >> 1;
      float alr = d_ald[(s * 32 + kmode) * 2], ali = d_ald[(s * 32 + kmode) * 2 + 1];
      float4 cv = acc[mt][j];
      int t0 = wg * 48 + mt * 16 + r;
      float re0 = alr * cv.x - ali * cv.y, im0 = alr * cv.y + ali * cv.x;
      float re1 = alr * cv.z - ali * cv.w, im1 = alr * cv.w + ali * cv.z;
      size_t e0 = base0 + (size_t)t0 * 64 + ncol;
      size_t e1 = base0 + (size_t)(t0 + 8) * 64 + ncol;
      __nv_bfloat16 h0r = __float2bfloat16_rn(re0), h0i = __float2bfloat16_rn(im0);
      __nv_bfloat16 h1r = __float2bfloat16_rn(re1), h1i = __float2bfloat16_rn(im1);
      *(unsigned*)(d_W2h + e0) = ((unsigned)__bfloat16_as_ushort(h0i) << 16) | __bfloat16_as_ushort(h0r);
      *(unsigned*)(d_W2h + e1) = ((unsigned)__bfloat16_as_ushort(h1i) << 16) | __bfloat16_as_ushort(h1r);
      *(unsigned*)(d_W2l + e0) = pkbf(re0 - __bfloat162float(h0r), im0 - __bfloat162float(h0i));
      *(unsigned*)(d_W2l + e1) = pkbf(re1 - __bfloat162float(h1r), im1 - __bfloat162float(h1i));
    }
  }
}

// K2: fused GEMM + scan + k-reduction, double-buffered staging.
__global__ void k_gemmU() {
  __shared__ unsigned Bph[2][16 * 72], Bpl[2][16 * 72];
  __shared__ float WsRe[12][32], WsIm[12][32];
  int bn = blockIdx.x, ub = blockIdx.y;
  int s = (ub == 0) ? 0 : (ub < 3) ? 1 : 2;
  int tid = threadIdx.x, wid = tid >> 5, lane = tid & 31;
  int r = lane >> 2, c = lane & 3;
  int ut = ub * 12 + wid;
  float4 acc[8];
#pragma unroll
  for (int j = 0; j < 8; j++) acc[j] = make_float4(0.f, 0.f, 0.f, 0.f);

  int pairsel = tid >> 7, t2 = tid & 127;
  int k2 = t2 >> 3, oc = t2 & 7;
  const __nv_bfloat16* bbase = pairsel ? d_W2l : d_W2h;
  uint4 va, vb;
  if (tid < 256) {
    const __nv_bfloat16* src = bbase + (size_t)(s * 256 + 2 * k2) * NCOL + bn * 64 + oc * 8;
    va = *(const uint4*)src;
    vb = *(const uint4*)(src + NCOL);
  }
  for (int ch = 0; ch < 8; ch++) {
    int bsel = ch & 1;
    if (tid < 256) {
      unsigned* dst = pairsel ? Bpl[bsel] : Bph[bsel];
      const unsigned* pa = (const unsigned*)&va;
      const unsigned* pb = (const unsigned*)&vb;
#pragma unroll
      for (int h2 = 0; h2 < 4; h2++) {
        int n0 = oc * 8 + h2 * 2, n1 = n0 + 1;
        dst[k2 * 72 + (n0 & 7) * 8 + (n0 >> 3)] = __byte_perm(pa[h2], pb[h2], 0x5410);
        dst[k2 * 72 + (n1 & 7) * 8 + (n1 >> 3)] = __byte_perm(pa[h2], pb[h2], 0x7632);
      }
    }
    __syncthreads();
    if (ch < 7 && tid < 256) {
      const __nv_bfloat16* src = bbase + (size_t)(s * 256 + (ch + 1) * 32 + 2 * k2) * NCOL + bn * 64 + oc * 8;
      va = *(const uint4*)src;
      vb = *(const uint4*)(src + NCOL);
    }
#pragma unroll
    for (int m = 0; m < 2; m++) {
      int mmg = ch * 2 + m;
      uint4 ah = d_HfH[(ut * 16 + mmg) * 32 + lane];
      uint4 al = d_HfL[(ut * 16 + mmg) * 32 + lane];
#pragma unroll
      for (int half = 0; half < 2; half++) {
        uint4 b0h = *(const uint4*)&Bph[bsel][(8 * m + c) * 72 + r * 8 + half * 4];
        uint4 b1h = *(const uint4*)&Bph[bsel][(8 * m + c + 4) * 72 + r * 8 + half * 4];
        uint4 b0l = *(const uint4*)&Bpl[bsel][(8 * m + c) * 72 + r * 8 + half * 4];
        uint4 b1l = *(const uint4*)&Bpl[bsel][(8 * m + c + 4) * 72 + r * 8 + half * 4];
        const unsigned* p0h = (const unsigned*)&b0h;
        const unsigned* p1h = (const unsigned*)&b1h;
        const unsigned* p0l = (const unsigned*)&b0l;
        const unsigned* p1l = (const unsigned*)&b1l;
#pragma unroll
        for (int j = 0; j < 4; j++) {
          int jj = half * 4 + j;
          mma16(acc[jj], ah, p0h[j], p1h[j]);
          mma16(acc[jj], ah, p0l[j], p1l[j]);
          mma16(acc[jj], al, p0h[j], p1h[j]);
        }
      }
    }
  }
  // ---------- fused scan epilogue ----------
  int T = 192 << s;
  int uoff = (s == 0) ? 0 : (s == 1) ? 192 : 576;
  int ul0 = ub * 192 - uoff + wid * 16;
  float pi2t = 6.2831853071795864f / (float)T;
#pragma unroll
  for (int j = 0; j < 8; j++) {
    int k = j * 4 + c;
    int u0 = ul0 + r, u1 = u0 + 8;
    float s0, c0, s1, c1;
    __sincosf(pi2t * (float)((u0 * k) % T), &s0, &c0);
    __sincosf(pi2t * (float)((u1 * k) % T), &s1, &c1);
    float re0 = c0 * acc[j].x + s0 * acc[j].y;
    float im0 = c0 * acc[j].y - s0 * acc[j].x;
    float re1 = c1 * acc[j].z + s1 * acc[j].w;
    float im1 = c1 * acc[j].w - s1 * acc[j].z;
    acc[j].x = re0; acc[j].y = im0; acc[j].z = re1; acc[j].w = im1;
  }
#pragma unroll
  for (int j = 0; j < 8; j++) {
    acc[j].x = scan_r(acc[j].x, r);
    acc[j].y = scan_r(acc[j].y, r);
    float t0re = __shfl_sync(0xffffffffu, acc[j].x, 28 + c);
    float t0im = __shfl_sync(0xffffffffu, acc[j].y, 28 + c);
    acc[j].z = scan_r(acc[j].z, r) + t0re;
    acc[j].w = scan_r(acc[j].w, r) + t0im;
  }
  if (r == 7) {
#pragma unroll
    for (int j = 0; j < 8; j++) { WsRe[wid][j * 4 + c] = acc[j].z; WsIm[wid][j * 4 + c] = acc[j].w; }
  }
  __syncthreads();
  if (wid == 0) {
    float runr = 0.f, runi = 0.f;
#pragma unroll
    for (int w = 0; w < 12; w++) {
      float tr = WsRe[w][lane], ti = WsIm[w][lane];
      WsRe[w][lane] = runr; WsIm[w][lane] = runi;
      runr += tr; runi += ti;
    }
    ((float2*)d_Bs)[(ub * 192 + bn) * 32 + lane] = make_float2(runr, runi);
  }
  __syncthreads();
  float g0 = 0.f, g1 = 0.f;
#pragma unroll
  for (int j = 0; j < 8; j++) {
    int k = j * 4 + c;
    float wre = WsRe[wid][k], wim = WsIm[wid][k];
    float pre0 = acc[j].x + wre, pim0 = acc[j].y + wim;
    float pre1 = acc[j].z + wre, pim1 = acc[j].w + wim;
    int m0 = ul0 + r, m1 = m0 + 8;
    int tau0 = T - 1 - m0, tau1 = T - 1 - m1;
    float sa, ca, sb, cb;
    __sincosf(pi2t * (float)((tau0 * k) % T), &sa, &ca);
    __sincosf(pi2t * (float)((tau1 * k) % T), &sb, &cb);
    g0 += ca * pre0 + sa * pim0;
    g1 += cb * pre1 + sb * pim1;
  }
  g0 += __shfl_xor_sync(0xffffffffu, g0, 1);
  g0 += __shfl_xor_sync(0xffffffffu, g0, 2);
  g1 += __shfl_xor_sync(0xffffffffu, g1, 1);
  g1 += __shfl_xor_sync(0xffffffffu, g1, 2);
  if (c == 0) {
    int m0 = ul0 + r;
    d_G[(size_t)(uoff + T - 1 - m0) * 192 + bn] = g0;
    d_G[(size_t)(uoff + T - 1 - (m0 + 8)) * 192 + bn] = g1;
  }
}

// K3: cross-block prefix seeds. One block per tau-row; twiddle computed once.
__global__ void k_fix() {
  int row = blockIdx.x;
  int tau, uoff, T, ubbase;
  if (row < 192) { tau = row; uoff = 192; T = 384; ubbase = 1; }
  else { tau = row - 192; uoff = 576; T = 768; ubbase = 3; }
  int m = T - 1 - tau;
  int lb = m / 192;
  int wid = threadIdx.x >> 5, lane = threadIdx.x & 31;
  float sn, cs;
  __sincosf((6.2831853071795864f / (float)T) * (float)((tau * lane) % T), &sn, &cs);
  float* grow = d_G + (size_t)(uoff + tau) * 192;
  for (int t = wid; t < 192; t += 8) {
    float cor = 0.f, coi = 0.f;
    for (int x = 0; x < lb; x++) {
      float2 v = ((const float2*)d_Bs)[((ubbase + x) * 192 + t) * 32 + lane];
      cor += v.x; coi += v.y;
    }
    float g = cs * cor + sn * coi;
#pragma unroll
    for (int off = 16; off; off >>= 1) g += __shfl_xor_sync(0xffffffffu, g, off);
    if (!lane) grow[t] += g;
  }
}

// K5: combine scales with mlp weights
__global__ void k_comb(const float* __restrict__ mw) {
  int idx = blockIdx.x * 256 + threadIdx.x;
  if (idx >= 768 * 192) return;
  int jj = idx / 192, t = idx % 192;
  float acc = mw[2] * d_G[(size_t)(576 + jj) * 192 + t];
  if (jj >= 384) acc += mw[1] * d_G[(size_t)(192 + jj - 384) * 192 + t];
  if (jj >= 576) acc += mw[0] * d_G[(size_t)(jj - 576) * 192 + t];
  d_Gc[idx] = acc;
}

// K6: out[b,t,d] = mlp_b + sum_j inputs[b,j,d] * Gc[j,t]
__global__ void k_out(const float* __restrict__ inp, const float* __restrict__ mb, float* __restrict__ out) {
  __shared__ float fs[4096];
  int b = blockIdx.y, tt = blockIdx.x;
  int tid = threadIdx.x, d = tid & 63, tq = tid >> 6;
  float acc[4] = {0.f, 0.f, 0.f, 0.f};
  const float* ib = inp + (size_t)b * 768 * 64;
  for (int j0 = 0; j0 < 768; j0 += 64) {
    __syncthreads();
    for (int e = tid; e < 4096; e += 256) fs[e] = ib[(size_t)j0 * 64 + e];
    __syncthreads();
    for (int jj = 0; jj < 64; jj++) {
      float f = fs[jj * 64 + d];
#pragma unroll
      for (int l = 0; l < 4; l++) {
        int t = tt * 16 + tq * 4 + l;
        acc[l] += f * d_Gc[(size_t)(j0 + jj) * 192 + t];
      }
    }
  }
  float bb = mb[0];
#pragma unroll
  for (int l = 0; l < 4; l++) {
    int t = tt * 16 + tq * 4 + l;
    out[((size_t)b * 192 + t) * 64 + d] = acc[l] + bb;
  }
}

extern "C" void kernel_launch(void* const* d_in, const int* in_sizes, int n_in,
                              void* d_out, int out_size) {
  const float* inputs = (const float*)d_in[0];
  const float* spec_wr = (const float*)d_in[1];
  const float* spec_wi = (const float*)d_in[2];
  const float* mlp_w = (const float*)d_in[3];
  const float* mlp_b = (const float*)d_in[4];
  float* out = (float*)d_out;

  k_copy<<<256, 256>>>(h_al, (const uint4*)h_HfH, (const uint4*)h_HfL,
                       (const uint4*)h_EfH, (const uint4*)h_EfL);
  k_w2<<<dim3(256, 3), 256>>>(spec_wr, spec_wi);
  k_gemmU<<<dim3(192, 7), 384>>>();
  k_fix<<<768, 256>>>();
  k_comb<<<(768 * 192 + 255) / 256, 256>>>(mlp_w);
  k_out<<<dim3(12, 8), 256>>>(inputs, mlp_b, out);
}